// round 2
// baseline (speedup 1.0000x reference)
#include <cuda_runtime.h>
#include <cuda_bf16.h>
#include <math.h>

#define BATCH 2
#define SEQL 2000
#define DM 256
#define DI 512
#define DS 16
#define RNK 16
#define NX 48          // RNK + 2*DS
#define NROWS (BATCH*SEQL)   // 4000

// ---------------- scratch (device globals; no allocations) ----------------
__device__ float g_h[NROWS*DM];      // residual stream
__device__ float g_ln[NROWS*DM];     // layernorm output
__device__ float g_xz[NROWS*2*DI];   // in_proj output (u | z)
__device__ float g_u[NROWS*DI];      // conv+silu output
__device__ float g_xdbc[NROWS*NX];   // x_proj output (dt_r | B | C)
__device__ float g_dt[NROWS*DI];     // softplus(dt)
__device__ float g_y[NROWS*DI];      // scan output (gated)

// ---------------- helpers ----------------
__device__ __forceinline__ float siluf(float x) {
    return x * __frcp_rn(1.f + __expf(-x));
}
__device__ __forceinline__ float softplusf(float x) {
    return (x > 20.f) ? x : log1pf(__expf(x));
}

// ---------------- embed ----------------
__global__ void embed_kernel(const float* __restrict__ x,
                             const float* __restrict__ bw,
                             const float* __restrict__ bb,
                             const float* __restrict__ ge,
                             const float* __restrict__ me) {
    int idx = blockIdx.x * blockDim.x + threadIdx.x;
    if (idx >= NROWS * DM) return;
    int d = idx & (DM - 1);
    int row = idx >> 8;
    int l = row % SEQL;
    g_h[idx] = x[row] * bw[d] + bb[d] + ge[l * DM + d] + me[d];
}

// ---------------- layernorm ----------------
__global__ void ln_kernel(const float* __restrict__ X,
                          const float* __restrict__ w,
                          const float* __restrict__ b,
                          float* __restrict__ Y) {
    __shared__ float sb1[8], sb2[8];
    int row = blockIdx.x;
    int d = threadIdx.x;
    float v = X[row * DM + d];
    float s1 = v, s2 = v * v;
    #pragma unroll
    for (int o = 16; o > 0; o >>= 1) {
        s1 += __shfl_xor_sync(0xffffffffu, s1, o);
        s2 += __shfl_xor_sync(0xffffffffu, s2, o);
    }
    int lane = d & 31, wid = d >> 5;
    if (lane == 0) { sb1[wid] = s1; sb2[wid] = s2; }
    __syncthreads();
    if (wid == 0) {
        float t1 = (lane < 8) ? sb1[lane] : 0.f;
        float t2 = (lane < 8) ? sb2[lane] : 0.f;
        #pragma unroll
        for (int o = 4; o > 0; o >>= 1) {
            t1 += __shfl_xor_sync(0xffffffffu, t1, o);
            t2 += __shfl_xor_sync(0xffffffffu, t2, o);
        }
        if (lane == 0) { sb1[0] = t1; sb2[0] = t2; }
    }
    __syncthreads();
    float mu = sb1[0] * (1.f / DM);
    float var = sb2[0] * (1.f / DM) - mu * mu;
    Y[row * DM + d] = (v - mu) * rsqrtf(var + 1e-5f) * w[d] + b[d];
}

// ---------------- optimized SGEMM: C[M,N] = A[M,K] * W[N,K]^T (+ res) ----------------
// Double-buffered smem, [k][m] layout (stride BM+4), 256 threads.
// BM in {64,128}, BN=64, BK=16. Per-thread: (BM/16) x 4 accumulators.
template<int BM, int BN>
__global__ void __launch_bounds__(256) gemm_nt_opt(const float* __restrict__ A,
                                                   const float* __restrict__ W,
                                                   float* __restrict__ C,
                                                   const float* __restrict__ res,
                                                   int M, int N, int K) {
    constexpr int BK = 16;
    constexpr int MR = BM / 16;          // 8 or 4
    constexpr int AV = BM / 64;          // float4 loads per thread for A (2 or 1)
    constexpr int BV = BN / 64;          // 1
    constexpr int LDA = BM + 4;
    constexpr int LDB = BN + 4;

    __shared__ float As[2][BK][LDA];
    __shared__ float Bs[2][BK][LDB];

    const int t = threadIdx.x;
    const int tx = t & 15, ty = t >> 4;
    const int m0 = blockIdx.y * BM, n0 = blockIdx.x * BN;

    float4 ra[AV], rb[BV];
    float acc[MR][4];
    #pragma unroll
    for (int i = 0; i < MR; i++)
        #pragma unroll
        for (int j = 0; j < 4; j++) acc[i][j] = 0.f;

    // ---- gmem tile loads into registers ----
    auto loadA = [&](int k0) {
        #pragma unroll
        for (int i = 0; i < AV; i++) {
            int p = t + i * 256;
            int m = p >> 2, kc = p & 3;
            int gr = m0 + m;
            ra[i] = (gr < M) ? *(const float4*)(A + (size_t)gr * K + k0 + kc * 4)
                             : make_float4(0.f, 0.f, 0.f, 0.f);
        }
    };
    auto loadB = [&](int k0) {
        #pragma unroll
        for (int i = 0; i < BV; i++) {
            int p = t + i * 256;
            int n = p >> 2, kc = p & 3;
            int gr = n0 + n;
            rb[i] = (gr < N) ? *(const float4*)(W + (size_t)gr * K + k0 + kc * 4)
                             : make_float4(0.f, 0.f, 0.f, 0.f);
        }
    };
    auto storeAB = [&](int buf) {
        #pragma unroll
        for (int i = 0; i < AV; i++) {
            int p = t + i * 256;
            int m = p >> 2, kc = p & 3;
            As[buf][kc * 4 + 0][m] = ra[i].x;
            As[buf][kc * 4 + 1][m] = ra[i].y;
            As[buf][kc * 4 + 2][m] = ra[i].z;
            As[buf][kc * 4 + 3][m] = ra[i].w;
        }
        #pragma unroll
        for (int i = 0; i < BV; i++) {
            int p = t + i * 256;
            int n = p >> 2, kc = p & 3;
            Bs[buf][kc * 4 + 0][n] = rb[i].x;
            Bs[buf][kc * 4 + 1][n] = rb[i].y;
            Bs[buf][kc * 4 + 2][n] = rb[i].z;
            Bs[buf][kc * 4 + 3][n] = rb[i].w;
        }
    };

    // ---- prologue ----
    loadA(0); loadB(0);
    storeAB(0);
    __syncthreads();

    const int nt = K / BK;
    for (int kt = 0; kt < nt; kt++) {
        int cur = kt & 1;
        if (kt + 1 < nt) { loadA((kt + 1) * BK); loadB((kt + 1) * BK); }

        #pragma unroll
        for (int kk = 0; kk < BK; kk++) {
            float a[MR], b[4];
            #pragma unroll
            for (int jj = 0; jj < MR / 4; jj++)
                *(float4*)&a[jj * 4] = *(const float4*)&As[cur][kk][ty * MR + jj * 4];
            *(float4*)&b[0] = *(const float4*)&Bs[cur][kk][tx * 4];
            #pragma unroll
            for (int i = 0; i < MR; i++)
                #pragma unroll
                for (int j = 0; j < 4; j++)
                    acc[i][j] = fmaf(a[i], b[j], acc[i][j]);
        }

        if (kt + 1 < nt) {
            storeAB(cur ^ 1);
            __syncthreads();
        }
    }

    // ---- epilogue ----
    #pragma unroll
    for (int i = 0; i < MR; i++) {
        int r = m0 + ty * MR + i;
        if (r >= M) continue;
        #pragma unroll
        for (int j = 0; j < 4; j++) {
            int c = n0 + tx * 4 + j;
            if (c >= N) continue;
            float v = acc[i][j];
            if (res) v += res[(size_t)r * N + c];
            C[(size_t)r * N + c] = v;
        }
    }
}

// ---------------- causal depthwise conv (taps=4) + silu ----------------
__global__ void conv_silu_kernel(const float* __restrict__ cw,
                                 const float* __restrict__ cb) {
    int idx = blockIdx.x * blockDim.x + threadIdx.x;
    if (idx >= NROWS * DI) return;
    int d = idx & (DI - 1);
    int row = idx >> 9;
    int l = row % SEQL;
    float acc = cb[d];
    #pragma unroll
    for (int k = 0; k < 4; k++) {
        int ls = l + k - 3;
        if (ls >= 0)
            acc = fmaf(g_xz[(size_t)(row + k - 3) * (2 * DI) + d], cw[d * 4 + k], acc);
    }
    g_u[idx] = siluf(acc);
}

// ---------------- dt = softplus(dt_r @ dtw^T + b) ----------------
__global__ void dt_kernel(const float* __restrict__ dtw,
                          const float* __restrict__ dtb) {
    __shared__ float s[RNK];
    int row = blockIdx.x;
    int d = threadIdx.x;
    if (d < RNK) s[d] = g_xdbc[row * NX + d];
    __syncthreads();
    float acc = dtb[d];
    #pragma unroll
    for (int r = 0; r < RNK; r++)
        acc = fmaf(s[r], dtw[d * RNK + r], acc);
    g_dt[row * DI + d] = softplusf(acc);
}

// ---------------- selective scan ----------------
__global__ void __launch_bounds__(128, 1) scan_kernel(const float* __restrict__ A_log,
                                                      const float* __restrict__ Dvec) {
    const int tid = threadIdx.x;
    const int g = tid >> 4, n = tid & 15;
    const int b = blockIdx.x >> 6;
    const int d = ((blockIdx.x & 63) << 3) + g;
    const float a = -__expf(A_log[d * DS + n]);
    const float Dv = Dvec[d];
    float hst = 0.f;
    const int rowbase = b * SEQL;

    float pdt[8], pu[8], pz[8], pB[8], pC[8];
    #pragma unroll
    for (int i = 0; i < 8; i++) {
        int base = rowbase + i;
        pdt[i] = g_dt[(size_t)base * DI + d];
        pu[i]  = g_u[(size_t)base * DI + d];
        pz[i]  = g_xz[(size_t)base * (2 * DI) + DI + d];
        pB[i]  = g_xdbc[base * NX + RNK + n];
        pC[i]  = g_xdbc[base * NX + RNK + DS + n];
    }
    for (int tb = 0; tb < SEQL; tb += 8) {
        float cdt[8], cu[8], cz[8], cB[8], cC[8];
        #pragma unroll
        for (int i = 0; i < 8; i++) {
            cdt[i] = pdt[i]; cu[i] = pu[i]; cz[i] = pz[i]; cB[i] = pB[i]; cC[i] = pC[i];
        }
        if (tb + 8 < SEQL) {
            #pragma unroll
            for (int i = 0; i < 8; i++) {
                int base = rowbase + tb + 8 + i;
                pdt[i] = g_dt[(size_t)base * DI + d];
                pu[i]  = g_u[(size_t)base * DI + d];
                pz[i]  = g_xz[(size_t)base * (2 * DI) + DI + d];
                pB[i]  = g_xdbc[base * NX + RNK + n];
                pC[i]  = g_xdbc[base * NX + RNK + DS + n];
            }
        }
        float e[8], duB[8];
        #pragma unroll
        for (int i = 0; i < 8; i++) {
            e[i]   = __expf(cdt[i] * a);
            duB[i] = cdt[i] * cu[i] * cB[i];
        }
        float part[8];
        #pragma unroll
        for (int i = 0; i < 8; i++) {
            hst = fmaf(e[i], hst, duB[i]);
            part[i] = hst * cC[i];
        }
        #pragma unroll
        for (int off = 8; off; off >>= 1)
            #pragma unroll
            for (int i = 0; i < 8; i++)
                part[i] += __shfl_xor_sync(0xffffffffu, part[i], off, 16);
        if (n == 0) {
            #pragma unroll
            for (int i = 0; i < 8; i++) {
                float yv = part[i] + cu[i] * Dv;
                g_y[(size_t)(rowbase + tb + i) * DI + d] = yv * siluf(cz[i]);
            }
        }
    }
}

// ---------------- head ----------------
__global__ void head_kernel(const float* __restrict__ hw,
                            const float* __restrict__ hb,
                            float* __restrict__ out) {
    __shared__ float sb[8];
    int row = blockIdx.x;
    int d = threadIdx.x;
    float v = g_ln[row * DM + d] * hw[d];
    #pragma unroll
    for (int o = 16; o > 0; o >>= 1) v += __shfl_xor_sync(0xffffffffu, v, o);
    int lane = d & 31, wid = d >> 5;
    if (lane == 0) sb[wid] = v;
    __syncthreads();
    if (wid == 0) {
        float t = (lane < 8) ? sb[lane] : 0.f;
        #pragma unroll
        for (int o = 4; o > 0; o >>= 1) t += __shfl_xor_sync(0xffffffffu, t, o);
        if (lane == 0) out[row] = t + hb[0];
    }
}

// ---------------- host orchestration ----------------
extern "C" void kernel_launch(void* const* d_in, const int* in_sizes, int n_in,
                              void* d_out, int out_size) {
    const float* x    = (const float*)d_in[0];
    const float* bw   = (const float*)d_in[1];
    const float* bb   = (const float*)d_in[2];
    const float* ge   = (const float*)d_in[3];
    const float* me   = (const float*)d_in[4];
    const float* lnw  = (const float*)d_in[5];
    const float* lnb  = (const float*)d_in[6];
    const float* ipw  = (const float*)d_in[7];
    const float* cw   = (const float*)d_in[8];
    const float* cb   = (const float*)d_in[9];
    const float* xpw  = (const float*)d_in[10];
    const float* dtw  = (const float*)d_in[11];
    const float* dtb  = (const float*)d_in[12];
    const float* alog = (const float*)d_in[13];
    const float* Dv   = (const float*)d_in[14];
    const float* opw  = (const float*)d_in[15];
    const float* fw   = (const float*)d_in[16];
    const float* fb   = (const float*)d_in[17];
    const float* hw   = (const float*)d_in[18];
    const float* hb   = (const float*)d_in[19];
    float* out = (float*)d_out;

    float *p_h, *p_ln, *p_xz, *p_u, *p_xdbc, *p_y;
    cudaGetSymbolAddress((void**)&p_h, g_h);
    cudaGetSymbolAddress((void**)&p_ln, g_ln);
    cudaGetSymbolAddress((void**)&p_xz, g_xz);
    cudaGetSymbolAddress((void**)&p_u, g_u);
    cudaGetSymbolAddress((void**)&p_xdbc, g_xdbc);
    cudaGetSymbolAddress((void**)&p_y, g_y);

    embed_kernel<<<(NROWS * DM + 255) / 256, 256>>>(x, bw, bb, ge, me);

    for (int i = 0; i < 4; i++) {
        ln_kernel<<<NROWS, DM>>>(p_h, lnw + i * DM, lnb + i * DM, p_ln);
        {   // in_proj: 4000x1024x256
            dim3 grid((2 * DI) / 64, (NROWS + 127) / 128);
            gemm_nt_opt<128, 64><<<grid, 256>>>(p_ln, ipw + (size_t)i * 2 * DI * DM,
                                                p_xz, nullptr, NROWS, 2 * DI, DM);
        }
        conv_silu_kernel<<<(NROWS * DI + 255) / 256, 256>>>(cw + i * DI * 4, cb + i * DI);
        {   // x_proj: 4000x48x512
            dim3 grid(1, (NROWS + 63) / 64);
            gemm_nt_opt<64, 64><<<grid, 256>>>(p_u, xpw + (size_t)i * NX * DI,
                                               p_xdbc, nullptr, NROWS, NX, DI);
        }
        dt_kernel<<<NROWS, DI>>>(dtw + (size_t)i * DI * RNK, dtb + i * DI);
        scan_kernel<<<128, 128>>>(alog + (size_t)i * DI * DS, Dv + i * DI);
        {   // out_proj + residual: 4000x256x512
            dim3 grid(DM / 64, (NROWS + 127) / 128);
            gemm_nt_opt<128, 64><<<grid, 256>>>(p_y, opw + (size_t)i * DM * DI,
                                                p_h, p_h, NROWS, DM, DI);
        }
    }

    ln_kernel<<<NROWS, DM>>>(p_h, fw, fb, p_ln);
    head_kernel<<<NROWS, DM>>>(hw, hb, out);
}

// round 3
// speedup vs baseline: 1.8995x; 1.8995x over previous
#include <cuda_runtime.h>
#include <cuda_bf16.h>
#include <math.h>
#include <stdint.h>

#define BATCH 2
#define SEQL 2000
#define DM 256
#define DI 512
#define DS 16
#define RNK 16
#define NX 48          // RNK + 2*DS
#define NROWS (BATCH*SEQL)   // 4000

// ---------------- scratch (device globals; no allocations) ----------------
__device__ float g_h[NROWS*DM];      // residual stream
__device__ float g_ln[NROWS*DM];     // layernorm output
__device__ float g_xz[NROWS*2*DI];   // in_proj output (u | z)
__device__ float g_u[NROWS*DI];      // conv+silu output
__device__ float g_xdbc[NROWS*NX];   // x_proj output (dt_r | B | C)
__device__ float g_dt[NROWS*DI];     // softplus(dt)
__device__ float g_y[NROWS*DI];      // scan output (gated)

// ---------------- helpers ----------------
__device__ __forceinline__ float siluf(float x) {
    return x * __frcp_rn(1.f + __expf(-x));
}
__device__ __forceinline__ float softplusf(float x) {
    return (x > 20.f) ? x : log1pf(__expf(x));
}
__device__ __forceinline__ float to_tf32(float x) {
    uint32_t u;
    asm("cvt.rna.tf32.f32 %0, %1;" : "=r"(u) : "f"(x));
    return __uint_as_float(u);
}

// ---------------- embed ----------------
__global__ void embed_kernel(const float* __restrict__ x,
                             const float* __restrict__ bw,
                             const float* __restrict__ bb,
                             const float* __restrict__ ge,
                             const float* __restrict__ me) {
    int idx = blockIdx.x * blockDim.x + threadIdx.x;
    if (idx >= NROWS * DM) return;
    int d = idx & (DM - 1);
    int row = idx >> 8;
    int l = row % SEQL;
    g_h[idx] = x[row] * bw[d] + bb[d] + ge[l * DM + d] + me[d];
}

// ---------------- layernorm ----------------
__global__ void ln_kernel(const float* __restrict__ X,
                          const float* __restrict__ w,
                          const float* __restrict__ b,
                          float* __restrict__ Y) {
    __shared__ float sb1[8], sb2[8];
    int row = blockIdx.x;
    int d = threadIdx.x;
    float v = X[row * DM + d];
    float s1 = v, s2 = v * v;
    #pragma unroll
    for (int o = 16; o > 0; o >>= 1) {
        s1 += __shfl_xor_sync(0xffffffffu, s1, o);
        s2 += __shfl_xor_sync(0xffffffffu, s2, o);
    }
    int lane = d & 31, wid = d >> 5;
    if (lane == 0) { sb1[wid] = s1; sb2[wid] = s2; }
    __syncthreads();
    if (wid == 0) {
        float t1 = (lane < 8) ? sb1[lane] : 0.f;
        float t2 = (lane < 8) ? sb2[lane] : 0.f;
        #pragma unroll
        for (int o = 4; o > 0; o >>= 1) {
            t1 += __shfl_xor_sync(0xffffffffu, t1, o);
            t2 += __shfl_xor_sync(0xffffffffu, t2, o);
        }
        if (lane == 0) { sb1[0] = t1; sb2[0] = t2; }
    }
    __syncthreads();
    float mu = sb1[0] * (1.f / DM);
    float var = sb2[0] * (1.f / DM) - mu * mu;
    Y[row * DM + d] = (v - mu) * rsqrtf(var + 1e-5f) * w[d] + b[d];
}

// ---------------- tf32 tensor-core GEMM: C[M,N] = A[M,K] * W[N,K]^T (+ res) ----------------
// BM=128, BN=64, BK=16. 256 threads = 8 warps in 4(M) x 2(N); warp tile 32x32
// = 2 x 4 m16n8k8 atoms. smem [row][k] with LDK=20 -> conflict-free frag LDS.
template<int BM, int BN>
__global__ void __launch_bounds__(256) gemm_tf32(const float* __restrict__ A,
                                                 const float* __restrict__ W,
                                                 float* __restrict__ C,
                                                 const float* __restrict__ res,
                                                 int M, int N, int K) {
    constexpr int BK = 16;
    constexpr int LDK = BK + 4;   // 20 floats

    __shared__ float As[2][BM][LDK];
    __shared__ float Bs[2][BN][LDK];

    const int t = threadIdx.x;
    const int lane = t & 31;
    const int warp = t >> 5;
    const int wm = (warp >> 1) * 32;      // warp M offset within block
    const int wn = (warp & 1) * 32;       // warp N offset within block
    const int m0 = blockIdx.y * BM;
    const int n0 = blockIdx.x * BN;
    const int lr = lane >> 2;             // 0..7
    const int lc = lane & 3;              // 0..3

    // gmem staging addresses
    const int srow = t >> 2;              // 0..63
    const int skc  = (t & 3) * 4;         // 0,4,8,12

    float acc[2][4][4];
    #pragma unroll
    for (int i = 0; i < 2; i++)
        #pragma unroll
        for (int j = 0; j < 4; j++)
            #pragma unroll
            for (int k = 0; k < 4; k++) acc[i][j][k] = 0.f;

    float4 ra0, ra1, rb0;
    const float4 z4 = make_float4(0.f, 0.f, 0.f, 0.f);

    // ---- prologue: load tile 0 ----
    {
        int ar = m0 + srow;
        ra0 = (ar < M) ? *(const float4*)(A + (size_t)ar * K + skc) : z4;
        int ar2 = ar + 64;
        ra1 = (ar2 < M) ? *(const float4*)(A + (size_t)ar2 * K + skc) : z4;
        int br = n0 + srow;
        rb0 = (br < N) ? *(const float4*)(W + (size_t)br * K + skc) : z4;
    }
    {
        float4 ca = make_float4(to_tf32(ra0.x), to_tf32(ra0.y), to_tf32(ra0.z), to_tf32(ra0.w));
        *(float4*)&As[0][srow][skc] = ca;
        float4 cb = make_float4(to_tf32(ra1.x), to_tf32(ra1.y), to_tf32(ra1.z), to_tf32(ra1.w));
        *(float4*)&As[0][srow + 64][skc] = cb;
        float4 cc = make_float4(to_tf32(rb0.x), to_tf32(rb0.y), to_tf32(rb0.z), to_tf32(rb0.w));
        *(float4*)&Bs[0][srow][skc] = cc;
    }
    __syncthreads();

    const int nt = K / BK;
    for (int kt = 0; kt < nt; kt++) {
        const int cur = kt & 1;
        if (kt + 1 < nt) {
            int k0 = (kt + 1) * BK;
            int ar = m0 + srow;
            ra0 = (ar < M) ? *(const float4*)(A + (size_t)ar * K + k0 + skc) : z4;
            int ar2 = ar + 64;
            ra1 = (ar2 < M) ? *(const float4*)(A + (size_t)ar2 * K + k0 + skc) : z4;
            int br = n0 + srow;
            rb0 = (br < N) ? *(const float4*)(W + (size_t)br * K + k0 + skc) : z4;
        }

        #pragma unroll
        for (int s = 0; s < 2; s++) {
            const int kk = s * 8;
            uint32_t af[2][4];
            #pragma unroll
            for (int ma = 0; ma < 2; ma++) {
                int rb = wm + ma * 16 + lr;
                af[ma][0] = __float_as_uint(As[cur][rb][kk + lc]);
                af[ma][1] = __float_as_uint(As[cur][rb + 8][kk + lc]);
                af[ma][2] = __float_as_uint(As[cur][rb][kk + 4 + lc]);
                af[ma][3] = __float_as_uint(As[cur][rb + 8][kk + 4 + lc]);
            }
            uint32_t bf[4][2];
            #pragma unroll
            for (int nb = 0; nb < 4; nb++) {
                int nr = wn + nb * 8 + lr;
                bf[nb][0] = __float_as_uint(Bs[cur][nr][kk + lc]);
                bf[nb][1] = __float_as_uint(Bs[cur][nr][kk + 4 + lc]);
            }
            #pragma unroll
            for (int ma = 0; ma < 2; ma++)
                #pragma unroll
                for (int nb = 0; nb < 4; nb++) {
                    asm volatile(
                        "mma.sync.aligned.m16n8k8.row.col.f32.tf32.tf32.f32 "
                        "{%0,%1,%2,%3}, {%4,%5,%6,%7}, {%8,%9}, {%0,%1,%2,%3};"
                        : "+f"(acc[ma][nb][0]), "+f"(acc[ma][nb][1]),
                          "+f"(acc[ma][nb][2]), "+f"(acc[ma][nb][3])
                        : "r"(af[ma][0]), "r"(af[ma][1]), "r"(af[ma][2]), "r"(af[ma][3]),
                          "r"(bf[nb][0]), "r"(bf[nb][1]));
                }
        }

        if (kt + 1 < nt) {
            const int nxt = cur ^ 1;
            float4 ca = make_float4(to_tf32(ra0.x), to_tf32(ra0.y), to_tf32(ra0.z), to_tf32(ra0.w));
            *(float4*)&As[nxt][srow][skc] = ca;
            float4 cb = make_float4(to_tf32(ra1.x), to_tf32(ra1.y), to_tf32(ra1.z), to_tf32(ra1.w));
            *(float4*)&As[nxt][srow + 64][skc] = cb;
            float4 cc = make_float4(to_tf32(rb0.x), to_tf32(rb0.y), to_tf32(rb0.z), to_tf32(rb0.w));
            *(float4*)&Bs[nxt][srow][skc] = cc;
            __syncthreads();
        }
    }

    // ---- epilogue: c0/c1 at (row, 2*lc), c2/c3 at (row+8, 2*lc) ----
    #pragma unroll
    for (int ma = 0; ma < 2; ma++) {
        #pragma unroll
        for (int nb = 0; nb < 4; nb++) {
            int r = m0 + wm + ma * 16 + lr;
            int c = n0 + wn + nb * 8 + 2 * lc;
            if (c < N) {
                if (r < M) {
                    float2 v = make_float2(acc[ma][nb][0], acc[ma][nb][1]);
                    if (res) {
                        const float2 rv = *(const float2*)(res + (size_t)r * N + c);
                        v.x += rv.x; v.y += rv.y;
                    }
                    *(float2*)(C + (size_t)r * N + c) = v;
                }
                int r2 = r + 8;
                if (r2 < M) {
                    float2 v = make_float2(acc[ma][nb][2], acc[ma][nb][3]);
                    if (res) {
                        const float2 rv = *(const float2*)(res + (size_t)r2 * N + c);
                        v.x += rv.x; v.y += rv.y;
                    }
                    *(float2*)(C + (size_t)r2 * N + c) = v;
                }
            }
        }
    }
}

// ---------------- causal depthwise conv (taps=4) + silu ----------------
__global__ void conv_silu_kernel(const float* __restrict__ cw,
                                 const float* __restrict__ cb) {
    int idx = blockIdx.x * blockDim.x + threadIdx.x;
    if (idx >= NROWS * DI) return;
    int d = idx & (DI - 1);
    int row = idx >> 9;
    int l = row % SEQL;
    float acc = cb[d];
    #pragma unroll
    for (int k = 0; k < 4; k++) {
        int ls = l + k - 3;
        if (ls >= 0)
            acc = fmaf(g_xz[(size_t)(row + k - 3) * (2 * DI) + d], cw[d * 4 + k], acc);
    }
    g_u[idx] = siluf(acc);
}

// ---------------- dt = softplus(dt_r @ dtw^T + b) ----------------
__global__ void dt_kernel(const float* __restrict__ dtw,
                          const float* __restrict__ dtb) {
    __shared__ float s[RNK];
    int row = blockIdx.x;
    int d = threadIdx.x;
    if (d < RNK) s[d] = g_xdbc[row * NX + d];
    __syncthreads();
    float acc = dtb[d];
    #pragma unroll
    for (int r = 0; r < RNK; r++)
        acc = fmaf(s[r], dtw[d * RNK + r], acc);
    g_dt[row * DI + d] = softplusf(acc);
}

// ---------------- selective scan ----------------
__global__ void __launch_bounds__(128, 1) scan_kernel(const float* __restrict__ A_log,
                                                      const float* __restrict__ Dvec) {
    const int tid = threadIdx.x;
    const int g = tid >> 4, n = tid & 15;
    const int b = blockIdx.x >> 6;
    const int d = ((blockIdx.x & 63) << 3) + g;
    const float a = -__expf(A_log[d * DS + n]);
    const float Dv = Dvec[d];
    float hst = 0.f;
    const int rowbase = b * SEQL;

    float pdt[8], pu[8], pz[8], pB[8], pC[8];
    #pragma unroll
    for (int i = 0; i < 8; i++) {
        int base = rowbase + i;
        pdt[i] = g_dt[(size_t)base * DI + d];
        pu[i]  = g_u[(size_t)base * DI + d];
        pz[i]  = g_xz[(size_t)base * (2 * DI) + DI + d];
        pB[i]  = g_xdbc[base * NX + RNK + n];
        pC[i]  = g_xdbc[base * NX + RNK + DS + n];
    }
    for (int tb = 0; tb < SEQL; tb += 8) {
        float cdt[8], cu[8], cz[8], cB[8], cC[8];
        #pragma unroll
        for (int i = 0; i < 8; i++) {
            cdt[i] = pdt[i]; cu[i] = pu[i]; cz[i] = pz[i]; cB[i] = pB[i]; cC[i] = pC[i];
        }
        if (tb + 8 < SEQL) {
            #pragma unroll
            for (int i = 0; i < 8; i++) {
                int base = rowbase + tb + 8 + i;
                pdt[i] = g_dt[(size_t)base * DI + d];
                pu[i]  = g_u[(size_t)base * DI + d];
                pz[i]  = g_xz[(size_t)base * (2 * DI) + DI + d];
                pB[i]  = g_xdbc[base * NX + RNK + n];
                pC[i]  = g_xdbc[base * NX + RNK + DS + n];
            }
        }
        float e[8], duB[8];
        #pragma unroll
        for (int i = 0; i < 8; i++) {
            e[i]   = __expf(cdt[i] * a);
            duB[i] = cdt[i] * cu[i] * cB[i];
        }
        float part[8];
        #pragma unroll
        for (int i = 0; i < 8; i++) {
            hst = fmaf(e[i], hst, duB[i]);
            part[i] = hst * cC[i];
        }
        #pragma unroll
        for (int off = 8; off; off >>= 1)
            #pragma unroll
            for (int i = 0; i < 8; i++)
                part[i] += __shfl_xor_sync(0xffffffffu, part[i], off, 16);
        if (n == 0) {
            #pragma unroll
            for (int i = 0; i < 8; i++) {
                float yv = part[i] + cu[i] * Dv;
                g_y[(size_t)(rowbase + tb + i) * DI + d] = yv * siluf(cz[i]);
            }
        }
    }
}

// ---------------- head ----------------
__global__ void head_kernel(const float* __restrict__ hw,
                            const float* __restrict__ hb,
                            float* __restrict__ out) {
    __shared__ float sb[8];
    int row = blockIdx.x;
    int d = threadIdx.x;
    float v = g_ln[row * DM + d] * hw[d];
    #pragma unroll
    for (int o = 16; o > 0; o >>= 1) v += __shfl_xor_sync(0xffffffffu, v, o);
    int lane = d & 31, wid = d >> 5;
    if (lane == 0) sb[wid] = v;
    __syncthreads();
    if (wid == 0) {
        float t = (lane < 8) ? sb[lane] : 0.f;
        #pragma unroll
        for (int o = 4; o > 0; o >>= 1) t += __shfl_xor_sync(0xffffffffu, t, o);
        if (lane == 0) out[row] = t + hb[0];
    }
}

// ---------------- host orchestration ----------------
extern "C" void kernel_launch(void* const* d_in, const int* in_sizes, int n_in,
                              void* d_out, int out_size) {
    const float* x    = (const float*)d_in[0];
    const float* bw   = (const float*)d_in[1];
    const float* bb   = (const float*)d_in[2];
    const float* ge   = (const float*)d_in[3];
    const float* me   = (const float*)d_in[4];
    const float* lnw  = (const float*)d_in[5];
    const float* lnb  = (const float*)d_in[6];
    const float* ipw  = (const float*)d_in[7];
    const float* cw   = (const float*)d_in[8];
    const float* cb   = (const float*)d_in[9];
    const float* xpw  = (const float*)d_in[10];
    const float* dtw  = (const float*)d_in[11];
    const float* dtb  = (const float*)d_in[12];
    const float* alog = (const float*)d_in[13];
    const float* Dv   = (const float*)d_in[14];
    const float* opw  = (const float*)d_in[15];
    const float* fw   = (const float*)d_in[16];
    const float* fb   = (const float*)d_in[17];
    const float* hw   = (const float*)d_in[18];
    const float* hb   = (const float*)d_in[19];
    float* out = (float*)d_out;

    float *p_h, *p_ln, *p_xz, *p_u, *p_xdbc, *p_y;
    cudaGetSymbolAddress((void**)&p_h, g_h);
    cudaGetSymbolAddress((void**)&p_ln, g_ln);
    cudaGetSymbolAddress((void**)&p_xz, g_xz);
    cudaGetSymbolAddress((void**)&p_u, g_u);
    cudaGetSymbolAddress((void**)&p_xdbc, g_xdbc);
    cudaGetSymbolAddress((void**)&p_y, g_y);

    embed_kernel<<<(NROWS * DM + 255) / 256, 256>>>(x, bw, bb, ge, me);

    for (int i = 0; i < 4; i++) {
        ln_kernel<<<NROWS, DM>>>(p_h, lnw + i * DM, lnb + i * DM, p_ln);
        {   // in_proj: 4000x1024x256
            dim3 grid((2 * DI) / 64, (NROWS + 127) / 128);
            gemm_tf32<128, 64><<<grid, 256>>>(p_ln, ipw + (size_t)i * 2 * DI * DM,
                                              p_xz, nullptr, NROWS, 2 * DI, DM);
        }
        conv_silu_kernel<<<(NROWS * DI + 255) / 256, 256>>>(cw + i * DI * 4, cb + i * DI);
        {   // x_proj: 4000x48x512
            dim3 grid(1, (NROWS + 127) / 128);
            gemm_tf32<128, 64><<<grid, 256>>>(p_u, xpw + (size_t)i * NX * DI,
                                              p_xdbc, nullptr, NROWS, NX, DI);
        }
        dt_kernel<<<NROWS, DI>>>(dtw + (size_t)i * DI * RNK, dtb + i * DI);
        scan_kernel<<<128, 128>>>(alog + (size_t)i * DI * DS, Dv + i * DI);
        {   // out_proj + residual: 4000x256x512
            dim3 grid(DM / 64, (NROWS + 127) / 128);
            gemm_tf32<128, 64><<<grid, 256>>>(p_y, opw + (size_t)i * DM * DI,
                                              p_h, p_h, NROWS, DM, DI);
        }
    }

    ln_kernel<<<NROWS, DM>>>(p_h, fw, fb, p_ln);
    head_kernel<<<NROWS, DM>>>(hw, hb, out);
}

// round 5
// speedup vs baseline: 2.0048x; 1.0554x over previous
#include <cuda_runtime.h>
#include <cuda_fp16.h>
#include <math.h>
#include <stdint.h>

#define BATCH 2
#define SEQL 2000
#define DM 256
#define DI 512
#define DS 16
#define RNK 16
#define NX 48          // RNK + 2*DS
#define NROWS (BATCH*SEQL)   // 4000

// ---------------- scratch (device globals; no allocations) ----------------
__device__ float g_h[NROWS*DM];      // residual stream
__device__ float g_ln[NROWS*DM];     // layernorm output (fp32, for head)
__device__ float g_xz[NROWS*2*DI];   // in_proj output (u | z)
__device__ float g_u[NROWS*DI];      // conv+silu output (fp32, x_proj input)
__device__ float g_xdbc[NROWS*NX];   // x_proj output (dt_r | B | C)
__device__ float g_dt[NROWS*DI];     // softplus(dt)

__device__ __align__(16) __half g_lnh[NROWS*DM];       // fp16 ln out (in_proj A)
__device__ __align__(16) __half g_yh [NROWS*DI];       // fp16 scan out (out_proj A)
__device__ __align__(16) __half g_wih[(size_t)4*1024*DM];  // fp16 in_proj W
__device__ __align__(16) __half g_woh[(size_t)4*DM*DI];    // fp16 out_proj W

// ---------------- helpers ----------------
__device__ __forceinline__ float siluf(float x) {
    return x * __frcp_rn(1.f + __expf(-x));
}
__device__ __forceinline__ float softplusf(float x) {
    return (x > 20.f) ? x : log1pf(__expf(x));
}
__device__ __forceinline__ uint32_t smem_u32(const void* p) {
    uint32_t a;
    asm("{ .reg .u64 t; cvta.to.shared.u64 t, %1; cvt.u32.u64 %0, t; }" : "=r"(a) : "l"(p));
    return a;
}
__device__ __forceinline__ void cp16(uint32_t dst, const void* src, bool valid) {
    int sz = valid ? 16 : 0;
    asm volatile("cp.async.ca.shared.global [%0], [%1], 16, %2;"
                 :: "r"(dst), "l"(src), "r"(sz));
}

// ---------------- embed ----------------
__global__ void embed_kernel(const float* __restrict__ x,
                             const float* __restrict__ bw,
                             const float* __restrict__ bb,
                             const float* __restrict__ ge,
                             const float* __restrict__ me) {
    int idx = blockIdx.x * blockDim.x + threadIdx.x;
    if (idx >= NROWS * DM) return;
    int d = idx & (DM - 1);
    int row = idx >> 8;
    int l = row % SEQL;
    g_h[idx] = x[row] * bw[d] + bb[d] + ge[l * DM + d] + me[d];
}

// ---------------- weight fp32 -> fp16 ----------------
__global__ void wconv_kernel(const float* __restrict__ W, __half* __restrict__ Wh, int n) {
    int idx = blockIdx.x * blockDim.x + threadIdx.x;
    if (idx < n) Wh[idx] = __float2half(W[idx]);
}

// ---------------- layernorm (fp32 out + optional fp16 out) ----------------
__global__ void ln_kernel(const float* __restrict__ X,
                          const float* __restrict__ w,
                          const float* __restrict__ b,
                          float* __restrict__ Y,
                          __half* __restrict__ Yh) {
    __shared__ float sb1[8], sb2[8];
    int row = blockIdx.x;
    int d = threadIdx.x;
    float v = X[row * DM + d];
    float s1 = v, s2 = v * v;
    #pragma unroll
    for (int o = 16; o > 0; o >>= 1) {
        s1 += __shfl_xor_sync(0xffffffffu, s1, o);
        s2 += __shfl_xor_sync(0xffffffffu, s2, o);
    }
    int lane = d & 31, wid = d >> 5;
    if (lane == 0) { sb1[wid] = s1; sb2[wid] = s2; }
    __syncthreads();
    if (wid == 0) {
        float t1 = (lane < 8) ? sb1[lane] : 0.f;
        float t2 = (lane < 8) ? sb2[lane] : 0.f;
        #pragma unroll
        for (int o = 4; o > 0; o >>= 1) {
            t1 += __shfl_xor_sync(0xffffffffu, t1, o);
            t2 += __shfl_xor_sync(0xffffffffu, t2, o);
        }
        if (lane == 0) { sb1[0] = t1; sb2[0] = t2; }
    }
    __syncthreads();
    float mu = sb1[0] * (1.f / DM);
    float var = sb2[0] * (1.f / DM) - mu * mu;
    float out = (v - mu) * rsqrtf(var + 1e-5f) * w[d] + b[d];
    Y[row * DM + d] = out;
    if (Yh) Yh[row * DM + d] = __float2half(out);
}

// ---------------- fp16 tensor-core GEMM: C[M,N] = A[M,K]*W[N,K]^T (+res) ----------------
// mma.sync m16n8k16 fp16 in / fp32 accum. BK=32, cp.async double buffer.
// 256 threads = 8 warps in WMG x WNG grid; smem [row][20 uints] (conflict-free frags).
template<int BM, int BN, int WMG, int WNG>
__global__ void __launch_bounds__(256) gemm_fp16(const __half* __restrict__ A,
                                                 const __half* __restrict__ W,
                                                 float* __restrict__ C,
                                                 const float* __restrict__ res,
                                                 int M, int N, int K) {
    constexpr int MA = BM / (WMG * 16);   // m-atoms per warp
    constexpr int NA = BN / (WNG * 8);    // n-atoms per warp
    constexpr int ACH = BM * 4 / 256;     // A 16B-chunks per thread per tile
    constexpr int BCH = BN * 4 / 256;

    __shared__ uint32_t As[2][BM][20];
    __shared__ uint32_t Bs[2][BN][20];

    const int t = threadIdx.x;
    const int lane = t & 31, warp = t >> 5;
    const int r4 = lane >> 2, q = lane & 3;
    const int mi = warp / WNG, ni = warp % WNG;
    const int wm = mi * (BM / WMG), wn = ni * (BN / WNG);
    const int m0 = blockIdx.y * BM, n0 = blockIdx.x * BN;

    const uint32_t sA = smem_u32(&As[0][0][0]);
    const uint32_t sB = smem_u32(&Bs[0][0][0]);
    constexpr uint32_t ABUF = BM * 20 * 4;
    constexpr uint32_t BBUF = BN * 20 * 4;

    float acc[MA][NA][4];
    #pragma unroll
    for (int i = 0; i < MA; i++)
        #pragma unroll
        for (int j = 0; j < NA; j++)
            #pragma unroll
            for (int k = 0; k < 4; k++) acc[i][j][k] = 0.f;

    const int nt = K >> 5;   // K / 32

    // tile loader (kt -> buffer buf)
    auto load_tile = [&](int kt, int buf) {
        #pragma unroll
        for (int j = 0; j < ACH; j++) {
            int id = t + j * 256;
            int row = id >> 2, seg = id & 3;
            int gr = m0 + row;
            cp16(sA + buf * ABUF + (row * 20 + seg * 4) * 4,
                 A + (size_t)gr * K + kt * 32 + seg * 8, gr < M);
        }
        #pragma unroll
        for (int j = 0; j < BCH; j++) {
            int id = t + j * 256;
            int row = id >> 2, seg = id & 3;
            int gr = n0 + row;
            cp16(sB + buf * BBUF + (row * 20 + seg * 4) * 4,
                 W + (size_t)gr * K + kt * 32 + seg * 8, gr < N);
        }
        asm volatile("cp.async.commit_group;");
    };

    load_tile(0, 0);

    for (int kt = 0; kt < nt; kt++) {
        const int buf = kt & 1;
        if (kt + 1 < nt) {
            load_tile(kt + 1, buf ^ 1);
            asm volatile("cp.async.wait_group 1;");
        } else {
            asm volatile("cp.async.wait_group 0;");
        }
        __syncthreads();

        #pragma unroll
        for (int ks = 0; ks < 2; ks++) {
            const int ku = ks * 8;
            uint32_t a[MA][4], b[NA][2];
            #pragma unroll
            for (int ma = 0; ma < MA; ma++) {
                int row = wm + ma * 16 + r4;
                a[ma][0] = As[buf][row][ku + q];
                a[ma][1] = As[buf][row + 8][ku + q];
                a[ma][2] = As[buf][row][ku + 4 + q];
                a[ma][3] = As[buf][row + 8][ku + 4 + q];
            }
            #pragma unroll
            for (int na = 0; na < NA; na++) {
                int col = wn + na * 8 + r4;
                b[na][0] = Bs[buf][col][ku + q];
                b[na][1] = Bs[buf][col][ku + 4 + q];
            }
            #pragma unroll
            for (int ma = 0; ma < MA; ma++)
                #pragma unroll
                for (int na = 0; na < NA; na++) {
                    asm volatile(
                        "mma.sync.aligned.m16n8k16.row.col.f32.f16.f16.f32 "
                        "{%0,%1,%2,%3}, {%4,%5,%6,%7}, {%8,%9}, {%0,%1,%2,%3};"
                        : "+f"(acc[ma][na][0]), "+f"(acc[ma][na][1]),
                          "+f"(acc[ma][na][2]), "+f"(acc[ma][na][3])
                        : "r"(a[ma][0]), "r"(a[ma][1]), "r"(a[ma][2]), "r"(a[ma][3]),
                          "r"(b[na][0]), "r"(b[na][1]));
                }
        }
        __syncthreads();
    }

    // epilogue
    #pragma unroll
    for (int ma = 0; ma < MA; ma++) {
        #pragma unroll
        for (int na = 0; na < NA; na++) {
            int r = m0 + wm + ma * 16 + r4;
            int c = n0 + wn + na * 8 + 2 * q;
            if (c < N) {
                if (r < M) {
                    float2 v = make_float2(acc[ma][na][0], acc[ma][na][1]);
                    if (res) {
                        float2 rv = *(const float2*)(res + (size_t)r * N + c);
                        v.x += rv.x; v.y += rv.y;
                    }
                    *(float2*)(C + (size_t)r * N + c) = v;
                }
                int r2 = r + 8;
                if (r2 < M) {
                    float2 v = make_float2(acc[ma][na][2], acc[ma][na][3]);
                    if (res) {
                        float2 rv = *(const float2*)(res + (size_t)r2 * N + c);
                        v.x += rv.x; v.y += rv.y;
                    }
                    *(float2*)(C + (size_t)r2 * N + c) = v;
                }
            }
        }
    }
}

// ---------------- fp32 SIMT GEMM (exact; used for x_proj only) ----------------
__global__ void __launch_bounds__(256) gemm_nt(const float* __restrict__ A,
                                               const float* __restrict__ W,
                                               float* __restrict__ C,
                                               int M, int N, int K) {
    __shared__ float As[16][64];
    __shared__ float Bs[16][64];
    int tx = threadIdx.x & 15, ty = threadIdx.x >> 4;
    int m0 = blockIdx.y * 64, n0 = blockIdx.x * 64;
    int lr = threadIdx.x >> 2;
    int lc = (threadIdx.x & 3) << 2;
    float acc[4][4] = {};
    for (int k0 = 0; k0 < K; k0 += 16) {
        float4 av = make_float4(0.f, 0.f, 0.f, 0.f);
        int ar = m0 + lr;
        if (ar < M) av = *(const float4*)(A + (size_t)ar * K + k0 + lc);
        As[lc + 0][lr] = av.x; As[lc + 1][lr] = av.y;
        As[lc + 2][lr] = av.z; As[lc + 3][lr] = av.w;
        float4 bv = make_float4(0.f, 0.f, 0.f, 0.f);
        int br = n0 + lr;
        if (br < N) bv = *(const float4*)(W + (size_t)br * K + k0 + lc);
        Bs[lc + 0][lr] = bv.x; Bs[lc + 1][lr] = bv.y;
        Bs[lc + 2][lr] = bv.z; Bs[lc + 3][lr] = bv.w;
        __syncthreads();
        #pragma unroll
        for (int kk = 0; kk < 16; kk++) {
            float4 a4 = *(const float4*)&As[kk][ty << 2];
            float4 b4 = *(const float4*)&Bs[kk][tx << 2];
            float ar4[4] = {a4.x, a4.y, a4.z, a4.w};
            float br4[4] = {b4.x, b4.y, b4.z, b4.w};
            #pragma unroll
            for (int i = 0; i < 4; i++)
                #pragma unroll
                for (int j = 0; j < 4; j++)
                    acc[i][j] = fmaf(ar4[i], br4[j], acc[i][j]);
        }
        __syncthreads();
    }
    #pragma unroll
    for (int i = 0; i < 4; i++) {
        int r = m0 + (ty << 2) + i;
        if (r >= M) continue;
        #pragma unroll
        for (int j = 0; j < 4; j++) {
            int c = n0 + (tx << 2) + j;
            if (c >= N) continue;
            C[(size_t)r * N + c] = acc[i][j];
        }
    }
}

// ---------------- causal depthwise conv (taps=4) + silu ----------------
__global__ void conv_silu_kernel(const float* __restrict__ cw,
                                 const float* __restrict__ cb) {
    int idx = blockIdx.x * blockDim.x + threadIdx.x;
    if (idx >= NROWS * DI) return;
    int d = idx & (DI - 1);
    int row = idx >> 9;
    int l = row % SEQL;
    float acc = cb[d];
    #pragma unroll
    for (int k = 0; k < 4; k++) {
        int ls = l + k - 3;
        if (ls >= 0)
            acc = fmaf(g_xz[(size_t)(row + k - 3) * (2 * DI) + d], cw[d * 4 + k], acc);
    }
    g_u[idx] = siluf(acc);
}

// ---------------- dt = softplus(dt_r @ dtw^T + b) ----------------
__global__ void dt_kernel(const float* __restrict__ dtw,
                          const float* __restrict__ dtb) {
    __shared__ float s[RNK];
    int row = blockIdx.x;
    int d = threadIdx.x;
    if (d < RNK) s[d] = g_xdbc[row * NX + d];
    __syncthreads();
    float acc = dtb[d];
    #pragma unroll
    for (int r = 0; r < RNK; r++)
        acc = fmaf(s[r], dtw[d * RNK + r], acc);
    g_dt[row * DI + d] = softplusf(acc);
}

// ---------------- selective scan (fp16 y out) ----------------
__global__ void __launch_bounds__(128, 1) scan_kernel(const float* __restrict__ A_log,
                                                      const float* __restrict__ Dvec) {
    const int tid = threadIdx.x;
    const int g = tid >> 4, n = tid & 15;
    const int b = blockIdx.x >> 6;
    const int d = ((blockIdx.x & 63) << 3) + g;
    const float a = -__expf(A_log[d * DS + n]);
    const float Dv = Dvec[d];
    float hst = 0.f;
    const int rowbase = b * SEQL;

    float pdt[8], pu[8], pz[8], pB[8], pC[8];
    #pragma unroll
    for (int i = 0; i < 8; i++) {
        int base = rowbase + i;
        pdt[i] = g_dt[(size_t)base * DI + d];
        pu[i]  = g_u[(size_t)base * DI + d];
        pz[i]  = g_xz[(size_t)base * (2 * DI) + DI + d];
        pB[i]  = g_xdbc[base * NX + RNK + n];
        pC[i]  = g_xdbc[base * NX + RNK + DS + n];
    }
    for (int tb = 0; tb < SEQL; tb += 8) {
        float cdt[8], cu[8], cz[8], cB[8], cC[8];
        #pragma unroll
        for (int i = 0; i < 8; i++) {
            cdt[i] = pdt[i]; cu[i] = pu[i]; cz[i] = pz[i]; cB[i] = pB[i]; cC[i] = pC[i];
        }
        if (tb + 8 < SEQL) {
            #pragma unroll
            for (int i = 0; i < 8; i++) {
                int base = rowbase + tb + 8 + i;
                pdt[i] = g_dt[(size_t)base * DI + d];
                pu[i]  = g_u[(size_t)base * DI + d];
                pz[i]  = g_xz[(size_t)base * (2 * DI) + DI + d];
                pB[i]  = g_xdbc[base * NX + RNK + n];
                pC[i]  = g_xdbc[base * NX + RNK + DS + n];
            }
        }
        float e[8], duB[8];
        #pragma unroll
        for (int i = 0; i < 8; i++) {
            e[i]   = __expf(cdt[i] * a);
            duB[i] = cdt[i] * cu[i] * cB[i];
        }
        float part[8];
        #pragma unroll
        for (int i = 0; i < 8; i++) {
            hst = fmaf(e[i], hst, duB[i]);
            part[i] = hst * cC[i];
        }
        #pragma unroll
        for (int off = 8; off; off >>= 1)
            #pragma unroll
            for (int i = 0; i < 8; i++)
                part[i] += __shfl_xor_sync(0xffffffffu, part[i], off, 16);
        if (n == 0) {
            #pragma unroll
            for (int i = 0; i < 8; i++) {
                float yv = part[i] + cu[i] * Dv;
                g_yh[(size_t)(rowbase + tb + i) * DI + d] = __float2half(yv * siluf(cz[i]));
            }
        }
    }
}

// ---------------- head ----------------
__global__ void head_kernel(const float* __restrict__ hw,
                            const float* __restrict__ hb,
                            float* __restrict__ out) {
    __shared__ float sb[8];
    int row = blockIdx.x;
    int d = threadIdx.x;
    float v = g_ln[row * DM + d] * hw[d];
    #pragma unroll
    for (int o = 16; o > 0; o >>= 1) v += __shfl_xor_sync(0xffffffffu, v, o);
    int lane = d & 31, wid = d >> 5;
    if (lane == 0) sb[wid] = v;
    __syncthreads();
    if (wid == 0) {
        float t = (lane < 8) ? sb[lane] : 0.f;
        #pragma unroll
        for (int o = 4; o > 0; o >>= 1) t += __shfl_xor_sync(0xffffffffu, t, o);
        if (lane == 0) out[row] = t + hb[0];
    }
}

// ---------------- host orchestration ----------------
extern "C" void kernel_launch(void* const* d_in, const int* in_sizes, int n_in,
                              void* d_out, int out_size) {
    const float* x    = (const float*)d_in[0];
    const float* bw   = (const float*)d_in[1];
    const float* bb   = (const float*)d_in[2];
    const float* ge   = (const float*)d_in[3];
    const float* me   = (const float*)d_in[4];
    const float* lnw  = (const float*)d_in[5];
    const float* lnb  = (const float*)d_in[6];
    const float* ipw  = (const float*)d_in[7];
    const float* cw   = (const float*)d_in[8];
    const float* cb   = (const float*)d_in[9];
    const float* xpw  = (const float*)d_in[10];
    const float* dtw  = (const float*)d_in[11];
    const float* dtb  = (const float*)d_in[12];
    const float* alog = (const float*)d_in[13];
    const float* Dv   = (const float*)d_in[14];
    const float* opw  = (const float*)d_in[15];
    const float* fw   = (const float*)d_in[16];
    const float* fb   = (const float*)d_in[17];
    const float* hw   = (const float*)d_in[18];
    const float* hb   = (const float*)d_in[19];
    float* out = (float*)d_out;

    float *p_h, *p_ln, *p_xz, *p_u, *p_xdbc;
    __half *p_lnh, *p_yh, *p_wih, *p_woh;
    cudaGetSymbolAddress((void**)&p_h, g_h);
    cudaGetSymbolAddress((void**)&p_ln, g_ln);
    cudaGetSymbolAddress((void**)&p_xz, g_xz);
    cudaGetSymbolAddress((void**)&p_u, g_u);
    cudaGetSymbolAddress((void**)&p_xdbc, g_xdbc);
    cudaGetSymbolAddress((void**)&p_lnh, g_lnh);
    cudaGetSymbolAddress((void**)&p_yh, g_yh);
    cudaGetSymbolAddress((void**)&p_wih, g_wih);
    cudaGetSymbolAddress((void**)&p_woh, g_woh);

    // launch 1
    embed_kernel<<<(NROWS * DM + 255) / 256, 256>>>(x, bw, bb, ge, me);

    for (int i = 0; i < 4; i++) {
        // launch 2 (i=0)
        ln_kernel<<<NROWS, DM>>>(p_h, lnw + i * DM, lnb + i * DM, p_ln, p_lnh);
        if (i == 0) {   // launch 3: fp16 weight conversion (all 4 layers)
            wconv_kernel<<<(4 * 1024 * DM + 255) / 256, 256>>>(ipw, p_wih, 4 * 1024 * DM);
        }
        {   // launch 4 (i=0): in_proj 4000x1024x256 — profiled slot
            dim3 grid(1024 / 128, (NROWS + 127) / 128);
            gemm_fp16<128, 128, 2, 4><<<grid, 256>>>(p_lnh, p_wih + (size_t)i * 1024 * DM,
                                                     p_xz, nullptr, NROWS, 1024, DM);
        }
        conv_silu_kernel<<<(NROWS * DI + 255) / 256, 256>>>(cw + i * DI * 4, cb + i * DI);
        if (i == 0) {
            wconv_kernel<<<(4 * DM * DI + 255) / 256, 256>>>(opw, p_woh, 4 * DM * DI);
        }
        {   // x_proj: exact fp32 (protects dt/scan path): 4000x48x512
            dim3 grid(1, (NROWS + 63) / 64);
            gemm_nt<<<grid, 256>>>(p_u, xpw + (size_t)i * NX * DI, p_xdbc,
                                   NROWS, NX, DI);
        }
        dt_kernel<<<NROWS, DI>>>(dtw + (size_t)i * DI * RNK, dtb + i * DI);
        scan_kernel<<<128, 128>>>(alog + (size_t)i * DI * DS, Dv + i * DI);
        {   // out_proj + residual: 4000x256x512
            dim3 grid(256 / 128, (NROWS + 63) / 64);
            gemm_fp16<64, 128, 2, 4><<<grid, 256>>>(p_yh, p_woh + (size_t)i * DM * DI,
                                                    p_h, p_h, NROWS, 256, DI);
        }
    }

    ln_kernel<<<NROWS, DM>>>(p_h, fw, fb, p_ln, nullptr);
    head_kernel<<<NROWS, DM>>>(hw, hb, out);
}

// round 6
// speedup vs baseline: 2.4095x; 1.2019x over previous
#include <cuda_runtime.h>
#include <cuda_fp16.h>
#include <math.h>
#include <stdint.h>

#define BATCH 2
#define SEQL 2000
#define DM 256
#define DI 512
#define DS 16
#define RNK 16
#define NX 48          // RNK + 2*DS
#define NROWS (BATCH*SEQL)   // 4000
#define NCH 25         // scan chunks
#define CL 80          // chunk length (NCH*CL == SEQL)

// ---------------- scratch (device globals; no allocations) ----------------
__device__ float g_h[NROWS*DM];      // residual stream
__device__ float g_ln[NROWS*DM];     // final layernorm out (head input)
__device__ float g_xz[NROWS*2*DI];   // in_proj output (u | z)
__device__ float g_u[NROWS*DI];      // conv+silu output fp32
__device__ float g_xdbc[NROWS*NX];   // x_proj output (dt_r | B | C)
__device__ float g_dt[NROWS*DI];     // softplus(dt)
__device__ float g_yp[NROWS*DI];     // scan pass1 partial y
__device__ float g_pe[BATCH*NCH*DI*DS];  // per-chunk prod(e)
__device__ float g_he[BATCH*NCH*DI*DS];  // per-chunk local h_end
__device__ float g_h0[BATCH*NCH*DI*DS];  // per-chunk true h_start

// fp16 hi/lo split operand arrays
__device__ __align__(16) __half g_lnh[NROWS*DM], g_lnl[NROWS*DM];
__device__ __align__(16) __half g_uh [NROWS*DI], g_ul [NROWS*DI];
__device__ __align__(16) __half g_yh [NROWS*DI], g_yl [NROWS*DI];
__device__ __align__(16) __half g_wih[(size_t)4*1024*DM], g_wil[(size_t)4*1024*DM];
__device__ __align__(16) __half g_wxh[(size_t)4*NX*DI],   g_wxl[(size_t)4*NX*DI];
__device__ __align__(16) __half g_woh[(size_t)4*DM*DI],   g_wol[(size_t)4*DM*DI];

// ---------------- helpers ----------------
__device__ __forceinline__ float siluf(float x) {
    return x * __frcp_rn(1.f + __expf(-x));
}
__device__ __forceinline__ float softplusf(float x) {
    return (x > 20.f) ? x : log1pf(__expf(x));
}
__device__ __forceinline__ void split_h(float v, __half& hi, __half& lo) {
    hi = __float2half(v);
    lo = __float2half(v - __half2float(hi));
}
__device__ __forceinline__ uint32_t smem_u32(const void* p) {
    uint32_t a;
    asm("{ .reg .u64 t; cvta.to.shared.u64 t, %1; cvt.u32.u64 %0, t; }" : "=r"(a) : "l"(p));
    return a;
}
__device__ __forceinline__ void cp16(uint32_t dst, const void* src, bool valid) {
    int sz = valid ? 16 : 0;
    asm volatile("cp.async.ca.shared.global [%0], [%1], 16, %2;"
                 :: "r"(dst), "l"(src), "r"(sz));
}

// ---------------- embed ----------------
__global__ void embed_kernel(const float* __restrict__ x,
                             const float* __restrict__ bw,
                             const float* __restrict__ bb,
                             const float* __restrict__ ge,
                             const float* __restrict__ me) {
    int idx = blockIdx.x * blockDim.x + threadIdx.x;
    if (idx >= NROWS * DM) return;
    int d = idx & (DM - 1);
    int row = idx >> 8;
    int l = row % SEQL;
    g_h[idx] = x[row] * bw[d] + bb[d] + ge[l * DM + d] + me[d];
}

// ---------------- weight split fp32 -> (fp16 hi, fp16 lo) ----------------
__global__ void wsplit_kernel(const float* __restrict__ W,
                              __half* __restrict__ Wh, __half* __restrict__ Wl, int n) {
    int idx = blockIdx.x * blockDim.x + threadIdx.x;
    if (idx >= n) return;
    __half hi, lo;
    split_h(W[idx], hi, lo);
    Wh[idx] = hi; Wl[idx] = lo;
}

// ---------------- layernorm (optional fp32 out, optional fp16 hi/lo out) ----------------
__global__ void ln_kernel(const float* __restrict__ X,
                          const float* __restrict__ w,
                          const float* __restrict__ b,
                          float* __restrict__ Y,
                          __half* __restrict__ Yh, __half* __restrict__ Yl) {
    __shared__ float sb1[8], sb2[8];
    int row = blockIdx.x;
    int d = threadIdx.x;
    float v = X[row * DM + d];
    float s1 = v, s2 = v * v;
    #pragma unroll
    for (int o = 16; o > 0; o >>= 1) {
        s1 += __shfl_xor_sync(0xffffffffu, s1, o);
        s2 += __shfl_xor_sync(0xffffffffu, s2, o);
    }
    int lane = d & 31, wid = d >> 5;
    if (lane == 0) { sb1[wid] = s1; sb2[wid] = s2; }
    __syncthreads();
    if (wid == 0) {
        float t1 = (lane < 8) ? sb1[lane] : 0.f;
        float t2 = (lane < 8) ? sb2[lane] : 0.f;
        #pragma unroll
        for (int o = 4; o > 0; o >>= 1) {
            t1 += __shfl_xor_sync(0xffffffffu, t1, o);
            t2 += __shfl_xor_sync(0xffffffffu, t2, o);
        }
        if (lane == 0) { sb1[0] = t1; sb2[0] = t2; }
    }
    __syncthreads();
    float mu = sb1[0] * (1.f / DM);
    float var = sb2[0] * (1.f / DM) - mu * mu;
    float out = (v - mu) * rsqrtf(var + 1e-5f) * w[d] + b[d];
    if (Y) Y[row * DM + d] = out;
    if (Yh) {
        __half hi, lo;
        split_h(out, hi, lo);
        Yh[row * DM + d] = hi;
        Yl[row * DM + d] = lo;
    }
}

// ---------------- split fp16 tensor GEMM: C = (Ah+Al)(Wh+Wl)^T (+res), 3-term ----------------
template<int BM, int BN, int WMG, int WNG>
__global__ void __launch_bounds__(256) gemm_sp(const __half* __restrict__ Ah,
                                               const __half* __restrict__ Al,
                                               const __half* __restrict__ Wh,
                                               const __half* __restrict__ Wl,
                                               float* __restrict__ C,
                                               const float* __restrict__ res,
                                               int M, int N, int K) {
    constexpr int MA = BM / (WMG * 16);
    constexpr int NA = BN / (WNG * 8);
    constexpr int ACH = BM * 4 / 256;     // 16B chunks per thread per array
    constexpr int BCH = BN * 4 / 256;

    extern __shared__ uint32_t dynsm[];
    uint32_t* AsB = dynsm;                      // [2][2][BM][20]
    uint32_t* BsB = dynsm + 4 * BM * 20;        // [2][2][BN][20]

    const int t = threadIdx.x;
    const int lane = t & 31, warp = t >> 5;
    const int r4 = lane >> 2, q = lane & 3;
    const int mi = warp / WNG, ni = warp % WNG;
    const int wm = mi * (BM / WMG), wn = ni * (BN / WNG);
    const int m0 = blockIdx.y * BM, n0 = blockIdx.x * BN;

    float acc[MA][NA][4];
    #pragma unroll
    for (int i = 0; i < MA; i++)
        #pragma unroll
        for (int j = 0; j < NA; j++)
            #pragma unroll
            for (int k = 0; k < 4; k++) acc[i][j][k] = 0.f;

    const int nt = K >> 5;

    auto load_tile = [&](int kt, int buf) {
        #pragma unroll
        for (int j = 0; j < ACH; j++) {
            int id = t + j * 256;
            int row = id >> 2, seg = id & 3;
            int gr = m0 + row;
            size_t go = (size_t)gr * K + kt * 32 + seg * 8;
            cp16(smem_u32(&AsB[((buf * 2 + 0) * BM + row) * 20 + seg * 4]), Ah + go, gr < M);
            cp16(smem_u32(&AsB[((buf * 2 + 1) * BM + row) * 20 + seg * 4]), Al + go, gr < M);
        }
        #pragma unroll
        for (int j = 0; j < BCH; j++) {
            int id = t + j * 256;
            int row = id >> 2, seg = id & 3;
            int gr = n0 + row;
            size_t go = (size_t)gr * K + kt * 32 + seg * 8;
            cp16(smem_u32(&BsB[((buf * 2 + 0) * BN + row) * 20 + seg * 4]), Wh + go, gr < N);
            cp16(smem_u32(&BsB[((buf * 2 + 1) * BN + row) * 20 + seg * 4]), Wl + go, gr < N);
        }
        asm volatile("cp.async.commit_group;");
    };

    load_tile(0, 0);

    for (int kt = 0; kt < nt; kt++) {
        const int buf = kt & 1;
        if (kt + 1 < nt) {
            load_tile(kt + 1, buf ^ 1);
            asm volatile("cp.async.wait_group 1;");
        } else {
            asm volatile("cp.async.wait_group 0;");
        }
        __syncthreads();

        #pragma unroll
        for (int ks = 0; ks < 2; ks++) {
            const int ku = ks * 8;
            uint32_t ah[MA][4], bh[NA][2], bl[NA][2], al[MA][4];
            #pragma unroll
            for (int ma = 0; ma < MA; ma++) {
                int row = wm + ma * 16 + r4;
                const uint32_t* basep = &AsB[((buf * 2 + 0) * BM) * 20];
                ah[ma][0] = basep[row * 20 + ku + q];
                ah[ma][1] = basep[(row + 8) * 20 + ku + q];
                ah[ma][2] = basep[row * 20 + ku + 4 + q];
                ah[ma][3] = basep[(row + 8) * 20 + ku + 4 + q];
                const uint32_t* baspl = &AsB[((buf * 2 + 1) * BM) * 20];
                al[ma][0] = baspl[row * 20 + ku + q];
                al[ma][1] = baspl[(row + 8) * 20 + ku + q];
                al[ma][2] = baspl[row * 20 + ku + 4 + q];
                al[ma][3] = baspl[(row + 8) * 20 + ku + 4 + q];
            }
            #pragma unroll
            for (int na = 0; na < NA; na++) {
                int col = wn + na * 8 + r4;
                const uint32_t* basep = &BsB[((buf * 2 + 0) * BN) * 20];
                bh[na][0] = basep[col * 20 + ku + q];
                bh[na][1] = basep[col * 20 + ku + 4 + q];
                const uint32_t* baspl = &BsB[((buf * 2 + 1) * BN) * 20];
                bl[na][0] = baspl[col * 20 + ku + q];
                bl[na][1] = baspl[col * 20 + ku + 4 + q];
            }
            #define DO_MMA(AF, BF)                                                        \
                _Pragma("unroll")                                                         \
                for (int ma = 0; ma < MA; ma++)                                           \
                    _Pragma("unroll")                                                     \
                    for (int na = 0; na < NA; na++) {                                     \
                        asm volatile(                                                     \
                            "mma.sync.aligned.m16n8k16.row.col.f32.f16.f16.f32 "          \
                            "{%0,%1,%2,%3}, {%4,%5,%6,%7}, {%8,%9}, {%0,%1,%2,%3};"       \
                            : "+f"(acc[ma][na][0]), "+f"(acc[ma][na][1]),                 \
                              "+f"(acc[ma][na][2]), "+f"(acc[ma][na][3])                  \
                            : "r"(AF[ma][0]), "r"(AF[ma][1]), "r"(AF[ma][2]),             \
                              "r"(AF[ma][3]), "r"(BF[na][0]), "r"(BF[na][1]));            \
                    }
            DO_MMA(ah, bh)
            DO_MMA(ah, bl)
            DO_MMA(al, bh)
            #undef DO_MMA
        }
        __syncthreads();
    }

    #pragma unroll
    for (int ma = 0; ma < MA; ma++) {
        #pragma unroll
        for (int na = 0; na < NA; na++) {
            int r = m0 + wm + ma * 16 + r4;
            int c = n0 + wn + na * 8 + 2 * q;
            if (c < N) {
                if (r < M) {
                    float2 v = make_float2(acc[ma][na][0], acc[ma][na][1]);
                    if (res) {
                        float2 rv = *(const float2*)(res + (size_t)r * N + c);
                        v.x += rv.x; v.y += rv.y;
                    }
                    *(float2*)(C + (size_t)r * N + c) = v;
                }
                int r2 = r + 8;
                if (r2 < M) {
                    float2 v = make_float2(acc[ma][na][2], acc[ma][na][3]);
                    if (res) {
                        float2 rv = *(const float2*)(res + (size_t)r2 * N + c);
                        v.x += rv.x; v.y += rv.y;
                    }
                    *(float2*)(C + (size_t)r2 * N + c) = v;
                }
            }
        }
    }
}

// ---------------- causal depthwise conv (taps=4) + silu ----------------
__global__ void conv_silu_kernel(const float* __restrict__ cw,
                                 const float* __restrict__ cb) {
    int idx = blockIdx.x * blockDim.x + threadIdx.x;
    if (idx >= NROWS * DI) return;
    int d = idx & (DI - 1);
    int row = idx >> 9;
    int l = row % SEQL;
    float acc = cb[d];
    #pragma unroll
    for (int k = 0; k < 4; k++) {
        int ls = l + k - 3;
        if (ls >= 0)
            acc = fmaf(g_xz[(size_t)(row + k - 3) * (2 * DI) + d], cw[d * 4 + k], acc);
    }
    float v = siluf(acc);
    g_u[idx] = v;
    __half hi, lo;
    split_h(v, hi, lo);
    g_uh[idx] = hi;
    g_ul[idx] = lo;
}

// ---------------- dt = softplus(dt_r @ dtw^T + b) ----------------
__global__ void dt_kernel(const float* __restrict__ dtw,
                          const float* __restrict__ dtb) {
    __shared__ float s[RNK];
    int row = blockIdx.x;
    int d = threadIdx.x;
    if (d < RNK) s[d] = g_xdbc[row * NX + d];
    __syncthreads();
    float acc = dtb[d];
    #pragma unroll
    for (int r = 0; r < RNK; r++)
        acc = fmaf(s[r], dtw[d * RNK + r], acc);
    g_dt[row * DI + d] = softplusf(acc);
}

// ---------------- scan pass 1: local scan per chunk ----------------
// grid = BATCH*NCH*64 blocks, 128 threads = 8 channels x 16 states.
__global__ void __launch_bounds__(128) scan1_kernel(const float* __restrict__ A_log) {
    const int tid = threadIdx.x;
    const int g = tid >> 4, n = tid & 15;
    int bi = blockIdx.x;
    const int b = bi / (NCH * 64);
    const int r = bi % (NCH * 64);
    const int ch = r >> 6;
    const int grp = r & 63;
    const int d = grp * 8 + g;
    const float a = -__expf(A_log[d * DS + n]);
    const int rowbase = b * SEQL + ch * CL;

    float h = 0.f, pe = 1.f;
    float pdt[8], pu[8], pB[8], pC[8];
    #pragma unroll
    for (int i = 0; i < 8; i++) {
        int base = rowbase + i;
        pdt[i] = g_dt[(size_t)base * DI + d];
        pu[i]  = g_u[(size_t)base * DI + d];
        pB[i]  = g_xdbc[base * NX + RNK + n];
        pC[i]  = g_xdbc[base * NX + RNK + DS + n];
    }
    for (int tb = 0; tb < CL; tb += 8) {
        float cdt[8], cu[8], cB[8], cC[8];
        #pragma unroll
        for (int i = 0; i < 8; i++) {
            cdt[i] = pdt[i]; cu[i] = pu[i]; cB[i] = pB[i]; cC[i] = pC[i];
        }
        if (tb + 8 < CL) {
            #pragma unroll
            for (int i = 0; i < 8; i++) {
                int base = rowbase + tb + 8 + i;
                pdt[i] = g_dt[(size_t)base * DI + d];
                pu[i]  = g_u[(size_t)base * DI + d];
                pB[i]  = g_xdbc[base * NX + RNK + n];
                pC[i]  = g_xdbc[base * NX + RNK + DS + n];
            }
        }
        float e[8], duB[8];
        #pragma unroll
        for (int i = 0; i < 8; i++) {
            e[i]   = __expf(cdt[i] * a);
            duB[i] = cdt[i] * cu[i] * cB[i];
        }
        float part[8];
        #pragma unroll
        for (int i = 0; i < 8; i++) {
            h = fmaf(e[i], h, duB[i]);
            pe *= e[i];
            part[i] = h * cC[i];
        }
        #pragma unroll
        for (int off = 8; off; off >>= 1)
            #pragma unroll
            for (int i = 0; i < 8; i++)
                part[i] += __shfl_xor_sync(0xffffffffu, part[i], off, 16);
        if (n == 0) {
            #pragma unroll
            for (int i = 0; i < 8; i++)
                g_yp[(size_t)(rowbase + tb + i) * DI + d] = part[i];
        }
    }
    int s = ((b * NCH + ch) * DI + d) * DS + n;
    g_pe[s] = pe;
    g_he[s] = h;
}

// ---------------- scan mid: chain chunk states (sequential over NCH) ----------------
__global__ void scanmid_kernel() {
    int idx = blockIdx.x * blockDim.x + threadIdx.x;
    if (idx >= BATCH * DI * DS) return;
    int b = idx / (DI * DS);
    int dn = idx % (DI * DS);
    float h = 0.f;
    for (int ch = 0; ch < NCH; ch++) {
        int s = (b * NCH + ch) * DI * DS + dn;
        g_h0[s] = h;
        h = g_pe[s] * h + g_he[s];
    }
}

// ---------------- scan pass 2: correction + gating, fp16 split out ----------------
__global__ void __launch_bounds__(128) scan2_kernel(const float* __restrict__ A_log,
                                                    const float* __restrict__ Dvec) {
    const int tid = threadIdx.x;
    const int g = tid >> 4, n = tid & 15;
    int bi = blockIdx.x;
    const int b = bi / (NCH * 64);
    const int r = bi % (NCH * 64);
    const int ch = r >> 6;
    const int grp = r & 63;
    const int d = grp * 8 + g;
    const float a = -__expf(A_log[d * DS + n]);
    const float Dv = Dvec[d];
    const int rowbase = b * SEQL + ch * CL;

    float P = g_h0[((b * NCH + ch) * DI + d) * DS + n];   // carries h0 * prod(e)

    float pdt[8], pu[8], pz[8], pC[8], pyp[8];
    #pragma unroll
    for (int i = 0; i < 8; i++) {
        int base = rowbase + i;
        pdt[i] = g_dt[(size_t)base * DI + d];
        pu[i]  = g_u[(size_t)base * DI + d];
        pz[i]  = g_xz[(size_t)base * (2 * DI) + DI + d];
        pC[i]  = g_xdbc[base * NX + RNK + DS + n];
        pyp[i] = g_yp[(size_t)base * DI + d];
    }
    for (int tb = 0; tb < CL; tb += 8) {
        float cdt[8], cu[8], cz[8], cC[8], cyp[8];
        #pragma unroll
        for (int i = 0; i < 8; i++) {
            cdt[i] = pdt[i]; cu[i] = pu[i]; cz[i] = pz[i]; cC[i] = pC[i]; cyp[i] = pyp[i];
        }
        if (tb + 8 < CL) {
            #pragma unroll
            for (int i = 0; i < 8; i++) {
                int base = rowbase + tb + 8 + i;
                pdt[i] = g_dt[(size_t)base * DI + d];
                pu[i]  = g_u[(size_t)base * DI + d];
                pz[i]  = g_xz[(size_t)base * (2 * DI) + DI + d];
                pC[i]  = g_xdbc[base * NX + RNK + DS + n];
                pyp[i] = g_yp[(size_t)base * DI + d];
            }
        }
        float e[8];
        #pragma unroll
        for (int i = 0; i < 8; i++)
            e[i] = __expf(cdt[i] * a);
        float c[8];
        #pragma unroll
        for (int i = 0; i < 8; i++) {
            P *= e[i];
            c[i] = cC[i] * P;
        }
        #pragma unroll
        for (int off = 8; off; off >>= 1)
            #pragma unroll
            for (int i = 0; i < 8; i++)
                c[i] += __shfl_xor_sync(0xffffffffu, c[i], off, 16);
        if (n == 0) {
            #pragma unroll
            for (int i = 0; i < 8; i++) {
                float y = cyp[i] + c[i] + cu[i] * Dv;
                float v = y * siluf(cz[i]);
                __half hi, lo;
                split_h(v, hi, lo);
                size_t o = (size_t)(rowbase + tb + i) * DI + d;
                g_yh[o] = hi;
                g_yl[o] = lo;
            }
        }
    }
}

// ---------------- head ----------------
__global__ void head_kernel(const float* __restrict__ hw,
                            const float* __restrict__ hb,
                            float* __restrict__ out) {
    __shared__ float sb[8];
    int row = blockIdx.x;
    int d = threadIdx.x;
    float v = g_ln[row * DM + d] * hw[d];
    #pragma unroll
    for (int o = 16; o > 0; o >>= 1) v += __shfl_xor_sync(0xffffffffu, v, o);
    int lane = d & 31, wid = d >> 5;
    if (lane == 0) sb[wid] = v;
    __syncthreads();
    if (wid == 0) {
        float t = (lane < 8) ? sb[lane] : 0.f;
        #pragma unroll
        for (int o = 4; o > 0; o >>= 1) t += __shfl_xor_sync(0xffffffffu, t, o);
        if (lane == 0) out[row] = t + hb[0];
    }
}

// ---------------- host orchestration ----------------
extern "C" void kernel_launch(void* const* d_in, const int* in_sizes, int n_in,
                              void* d_out, int out_size) {
    const float* x    = (const float*)d_in[0];
    const float* bw   = (const float*)d_in[1];
    const float* bb   = (const float*)d_in[2];
    const float* ge   = (const float*)d_in[3];
    const float* me   = (const float*)d_in[4];
    const float* lnw  = (const float*)d_in[5];
    const float* lnb  = (const float*)d_in[6];
    const float* ipw  = (const float*)d_in[7];
    const float* cw   = (const float*)d_in[8];
    const float* cb   = (const float*)d_in[9];
    const float* xpw  = (const float*)d_in[10];
    const float* dtw  = (const float*)d_in[11];
    const float* dtb  = (const float*)d_in[12];
    const float* alog = (const float*)d_in[13];
    const float* Dv   = (const float*)d_in[14];
    const float* opw  = (const float*)d_in[15];
    const float* fw   = (const float*)d_in[16];
    const float* fb   = (const float*)d_in[17];
    const float* hw   = (const float*)d_in[18];
    const float* hb   = (const float*)d_in[19];
    float* out = (float*)d_out;

    float *p_h, *p_ln, *p_xz, *p_xdbc;
    __half *p_lnh, *p_lnl, *p_uh, *p_ul, *p_yh, *p_yl;
    __half *p_wih, *p_wil, *p_wxh, *p_wxl, *p_woh, *p_wol;
    cudaGetSymbolAddress((void**)&p_h, g_h);
    cudaGetSymbolAddress((void**)&p_ln, g_ln);
    cudaGetSymbolAddress((void**)&p_xz, g_xz);
    cudaGetSymbolAddress((void**)&p_xdbc, g_xdbc);
    cudaGetSymbolAddress((void**)&p_lnh, g_lnh);
    cudaGetSymbolAddress((void**)&p_lnl, g_lnl);
    cudaGetSymbolAddress((void**)&p_uh, g_uh);
    cudaGetSymbolAddress((void**)&p_ul, g_ul);
    cudaGetSymbolAddress((void**)&p_yh, g_yh);
    cudaGetSymbolAddress((void**)&p_yl, g_yl);
    cudaGetSymbolAddress((void**)&p_wih, g_wih);
    cudaGetSymbolAddress((void**)&p_wil, g_wil);
    cudaGetSymbolAddress((void**)&p_wxh, g_wxh);
    cudaGetSymbolAddress((void**)&p_wxl, g_wxl);
    cudaGetSymbolAddress((void**)&p_woh, g_woh);
    cudaGetSymbolAddress((void**)&p_wol, g_wol);

    const int SM_IN  = (4 * 128 * 20 + 4 * 128 * 20) * 4;  // 81920
    const int SM_X   = (4 * 64 * 20 + 4 * 64 * 20) * 4;    // 40960
    const int SM_OUT = (4 * 64 * 20 + 4 * 128 * 20) * 4;   // 61440
    cudaFuncSetAttribute(gemm_sp<128, 128, 2, 4>,
                         cudaFuncAttributeMaxDynamicSharedMemorySize, SM_IN);
    cudaFuncSetAttribute(gemm_sp<64, 64, 2, 4>,
                         cudaFuncAttributeMaxDynamicSharedMemorySize, SM_X);
    cudaFuncSetAttribute(gemm_sp<64, 128, 2, 4>,
                         cudaFuncAttributeMaxDynamicSharedMemorySize, SM_OUT);

    // launch 1
    embed_kernel<<<(NROWS * DM + 255) / 256, 256>>>(x, bw, bb, ge, me);
    // launch 2
    wsplit_kernel<<<(4 * 1024 * DM + 255) / 256, 256>>>(ipw, p_wih, p_wil, 4 * 1024 * DM);

    const int SCAN_GRID = BATCH * NCH * 64;   // 3200

    for (int i = 0; i < 4; i++) {
        // launch 3 (i=0)
        ln_kernel<<<NROWS, DM>>>(p_h, lnw + i * DM, lnb + i * DM, nullptr, p_lnh, p_lnl);
        {   // launch 4 (i=0): in_proj — profiled slot
            dim3 grid(1024 / 128, (NROWS + 127) / 128);
            gemm_sp<128, 128, 2, 4><<<grid, 256, SM_IN>>>(
                p_lnh, p_lnl, p_wih + (size_t)i * 1024 * DM, p_wil + (size_t)i * 1024 * DM,
                p_xz, nullptr, NROWS, 1024, DM);
        }
        if (i == 0) {
            wsplit_kernel<<<(4 * NX * DI + 255) / 256, 256>>>(xpw, p_wxh, p_wxl, 4 * NX * DI);
            wsplit_kernel<<<(4 * DM * DI + 255) / 256, 256>>>(opw, p_woh, p_wol, 4 * DM * DI);
        }
        conv_silu_kernel<<<(NROWS * DI + 255) / 256, 256>>>(cw + i * DI * 4, cb + i * DI);
        {   // x_proj: M=4000, N=48, K=512
            dim3 grid(1, (NROWS + 63) / 64);
            gemm_sp<64, 64, 2, 4><<<grid, 256, SM_X>>>(
                p_uh, p_ul, p_wxh + (size_t)i * NX * DI, p_wxl + (size_t)i * NX * DI,
                p_xdbc, nullptr, NROWS, NX, DI);
        }
        dt_kernel<<<NROWS, DI>>>(dtw + (size_t)i * DI * RNK, dtb + i * DI);
        scan1_kernel<<<SCAN_GRID, 128>>>(alog + (size_t)i * DI * DS);
        scanmid_kernel<<<(BATCH * DI * DS + 255) / 256, 256>>>();
        scan2_kernel<<<SCAN_GRID, 128>>>(alog + (size_t)i * DI * DS, Dv + i * DI);
        {   // out_proj + residual: M=4000, N=256, K=512
            dim3 grid(256 / 128, (NROWS + 63) / 64);
            gemm_sp<64, 128, 2, 4><<<grid, 256, SM_OUT>>>(
                p_yh, p_yl, p_woh + (size_t)i * DM * DI, p_wol + (size_t)i * DM * DI,
                p_h, p_h, NROWS, 256, DI);
        }
    }

    ln_kernel<<<NROWS, DM>>>(p_h, fw, fb, p_ln, nullptr, nullptr);
    head_kernel<<<NROWS, DM>>>(hw, hb, out);
}

// round 7
// speedup vs baseline: 2.5703x; 1.0668x over previous
#include <cuda_runtime.h>
#include <cuda_fp16.h>
#include <math.h>
#include <stdint.h>

#define BATCH 2
#define SEQL 2000
#define DM 256
#define DI 512
#define DS 16
#define RNK 16
#define NROWS (BATCH*SEQL)   // 4000
#define NCH 25               // scan chunks
#define CL 80                // chunk length
#define NBIG 544             // 32 (B|C) + 512 (dt)

// ---------------- scratch (device globals; no allocations) ----------------
__device__ float g_h[NROWS*DM];      // residual stream
__device__ float g_ln[NROWS*DM];     // final layernorm out (head input)
__device__ float g_xz[NROWS*2*DI];   // in_proj output (u | z)
__device__ float g_u[NROWS*DI];      // conv+silu output fp32
__device__ float g_bc[NROWS*32];     // x_proj B|C compact
__device__ float g_dt[NROWS*DI];     // softplus(dt)
__device__ float g_yp[NROWS*DI];     // scan pass1 partial y
__device__ float g_pe[BATCH*NCH*DI*DS];
__device__ float g_he[BATCH*NCH*DI*DS];
__device__ float g_h0[BATCH*NCH*DI*DS];

// fp16 hi/lo split operands
__device__ __align__(16) __half g_lnh[NROWS*DM], g_lnl[NROWS*DM];
__device__ __align__(16) __half g_uh [NROWS*DI], g_ul [NROWS*DI];
__device__ __align__(16) __half g_yh [NROWS*DI], g_yl [NROWS*DI];
__device__ __align__(16) __half g_wih[(size_t)4*1024*DM], g_wil[(size_t)4*1024*DM];
__device__ __align__(16) __half g_wbh[(size_t)4*NBIG*DI], g_wbl[(size_t)4*NBIG*DI];
__device__ __align__(16) __half g_woh[(size_t)4*DM*DI],   g_wol[(size_t)4*DM*DI];

// ---------------- helpers ----------------
__device__ __forceinline__ float siluf(float x) {
    return x * __frcp_rn(1.f + __expf(-x));
}
__device__ __forceinline__ float softplus_fast(float x) {
    return fmaxf(x, 0.f) + __logf(1.f + __expf(-fabsf(x)));
}
__device__ __forceinline__ void split_h(float v, __half& hi, __half& lo) {
    hi = __float2half(v);
    lo = __float2half(v - __half2float(hi));
}
__device__ __forceinline__ uint32_t smem_u32(const void* p) {
    uint32_t a;
    asm("{ .reg .u64 t; cvta.to.shared.u64 t, %1; cvt.u32.u64 %0, t; }" : "=r"(a) : "l"(p));
    return a;
}
__device__ __forceinline__ void cp16(uint32_t dst, const void* src, bool valid) {
    int sz = valid ? 16 : 0;
    asm volatile("cp.async.ca.shared.global [%0], [%1], 16, %2;"
                 :: "r"(dst), "l"(src), "r"(sz));
}

// ---------------- embed ----------------
__global__ void embed_kernel(const float* __restrict__ x,
                             const float* __restrict__ bw,
                             const float* __restrict__ bb,
                             const float* __restrict__ ge,
                             const float* __restrict__ me) {
    int idx = blockIdx.x * blockDim.x + threadIdx.x;
    if (idx >= NROWS * DM) return;
    int d = idx & (DM - 1);
    int row = idx >> 8;
    int l = row % SEQL;
    g_h[idx] = x[row] * bw[d] + bb[d] + ge[l * DM + d] + me[d];
}

// ---------------- weight split fp32 -> (fp16 hi, lo) ----------------
__global__ void wsplit_kernel(const float* __restrict__ W,
                              __half* __restrict__ Wh, __half* __restrict__ Wl, int n) {
    int idx = blockIdx.x * blockDim.x + threadIdx.x;
    if (idx >= n) return;
    __half hi, lo;
    split_h(W[idx], hi, lo);
    Wh[idx] = hi; Wl[idx] = lo;
}

// ---------------- build W_big = [xp_w rows 16..47 | dt_w @ xp_w rows 0..15] ----------------
__global__ void wbig_kernel(const float* __restrict__ xpw,
                            const float* __restrict__ dtpw) {
    int bid = blockIdx.x;            // l*NBIG + j
    int l = bid / NBIG, j = bid % NBIG;
    int t = threadIdx.x;
    __shared__ float s[RNK];
    const float* xp = xpw + (size_t)l * 48 * DI;
    size_t obase = ((size_t)l * NBIG + j) * DI;
    if (j < 32) {
        for (int k = t; k < DI; k += 256) {
            __half hi, lo;
            split_h(xp[(16 + j) * DI + k], hi, lo);
            g_wbh[obase + k] = hi; g_wbl[obase + k] = lo;
        }
    } else {
        int d = j - 32;
        if (t < RNK) s[t] = dtpw[((size_t)l * DI + d) * RNK + t];
        __syncthreads();
        for (int k = t; k < DI; k += 256) {
            float acc = 0.f;
            #pragma unroll
            for (int r = 0; r < RNK; r++)
                acc = fmaf(s[r], xp[r * DI + k], acc);
            __half hi, lo;
            split_h(acc, hi, lo);
            g_wbh[obase + k] = hi; g_wbl[obase + k] = lo;
        }
    }
}

// ---------------- layernorm: warp per row, no block barriers ----------------
__global__ void __launch_bounds__(256) ln_kernel(const float* __restrict__ X,
                                                 const float* __restrict__ w,
                                                 const float* __restrict__ b,
                                                 float* __restrict__ Y,
                                                 __half* __restrict__ Yh,
                                                 __half* __restrict__ Yl) {
    int warp = threadIdx.x >> 5, lane = threadIdx.x & 31;
    int row = blockIdx.x * 8 + warp;
    if (row >= NROWS) return;
    const float* xr = X + (size_t)row * DM + lane * 8;
    float4 v0 = *(const float4*)xr;
    float4 v1 = *(const float4*)(xr + 4);
    float va[8] = {v0.x, v0.y, v0.z, v0.w, v1.x, v1.y, v1.z, v1.w};
    float s1 = 0.f, s2 = 0.f;
    #pragma unroll
    for (int i = 0; i < 8; i++) { s1 += va[i]; s2 += va[i] * va[i]; }
    #pragma unroll
    for (int o = 16; o > 0; o >>= 1) {
        s1 += __shfl_xor_sync(0xffffffffu, s1, o);
        s2 += __shfl_xor_sync(0xffffffffu, s2, o);
    }
    float mu = s1 * (1.f / DM);
    float var = s2 * (1.f / DM) - mu * mu;
    float rs = rsqrtf(var + 1e-5f);
    float4 w0 = *(const float4*)(w + lane * 8);
    float4 w1 = *(const float4*)(w + lane * 8 + 4);
    float4 b0 = *(const float4*)(b + lane * 8);
    float4 b1 = *(const float4*)(b + lane * 8 + 4);
    float wa[8] = {w0.x, w0.y, w0.z, w0.w, w1.x, w1.y, w1.z, w1.w};
    float ba[8] = {b0.x, b0.y, b0.z, b0.w, b1.x, b1.y, b1.z, b1.w};
    float oa[8];
    #pragma unroll
    for (int i = 0; i < 8; i++) oa[i] = (va[i] - mu) * rs * wa[i] + ba[i];
    if (Y) {
        float* yr = Y + (size_t)row * DM + lane * 8;
        *(float4*)yr = make_float4(oa[0], oa[1], oa[2], oa[3]);
        *(float4*)(yr + 4) = make_float4(oa[4], oa[5], oa[6], oa[7]);
    }
    if (Yh) {
        __half hh[8], ll[8];
        #pragma unroll
        for (int i = 0; i < 8; i++) split_h(oa[i], hh[i], ll[i]);
        *(uint4*)(Yh + (size_t)row * DM + lane * 8) = *(uint4*)hh;
        *(uint4*)(Yl + (size_t)row * DM + lane * 8) = *(uint4*)ll;
    }
}

// ---------------- split fp16 tensor GEMM, 3-term: C = (Ah+Al)(Wh+Wl)^T ----------------
// MODE 0: plain store. MODE 1: += res. MODE 2: col<32 -> BC buf; col>=32 -> softplus(v+bias)->DT.
template<int BM, int BN, int WMG, int WNG, int MODE>
__global__ void __launch_bounds__(256) gemm_sp(const __half* __restrict__ Ah,
                                               const __half* __restrict__ Al,
                                               const __half* __restrict__ Wh,
                                               const __half* __restrict__ Wl,
                                               float* __restrict__ C,
                                               const float* __restrict__ aux,
                                               float* __restrict__ C2,
                                               int M, int N, int K) {
    constexpr int MA = BM / (WMG * 16);
    constexpr int NA = BN / (WNG * 8);
    constexpr int ACH = BM * 4 / 256;
    constexpr int BCH = BN * 4 / 256;

    extern __shared__ uint32_t dynsm[];
    uint32_t* AsB = dynsm;                 // [2][2][BM][20]
    uint32_t* BsB = dynsm + 4 * BM * 20;   // [2][2][BN][20]

    const int t = threadIdx.x;
    const int lane = t & 31, warp = t >> 5;
    const int r4 = lane >> 2, q = lane & 3;
    const int mi = warp / WNG, ni = warp % WNG;
    const int wm = mi * (BM / WMG), wn = ni * (BN / WNG);
    const int m0 = blockIdx.y * BM, n0 = blockIdx.x * BN;

    float acc[MA][NA][4];
    #pragma unroll
    for (int i = 0; i < MA; i++)
        #pragma unroll
        for (int j = 0; j < NA; j++)
            #pragma unroll
            for (int k = 0; k < 4; k++) acc[i][j][k] = 0.f;

    const int nt = K >> 5;

    auto load_tile = [&](int kt, int buf) {
        #pragma unroll
        for (int j = 0; j < ACH; j++) {
            int id = t + j * 256;
            int row = id >> 2, seg = id & 3;
            int gr = m0 + row;
            size_t go = (size_t)gr * K + kt * 32 + seg * 8;
            cp16(smem_u32(&AsB[((buf * 2 + 0) * BM + row) * 20 + seg * 4]), Ah + go, gr < M);
            cp16(smem_u32(&AsB[((buf * 2 + 1) * BM + row) * 20 + seg * 4]), Al + go, gr < M);
        }
        #pragma unroll
        for (int j = 0; j < BCH; j++) {
            int id = t + j * 256;
            int row = id >> 2, seg = id & 3;
            int gr = n0 + row;
            size_t go = (size_t)gr * K + kt * 32 + seg * 8;
            cp16(smem_u32(&BsB[((buf * 2 + 0) * BN + row) * 20 + seg * 4]), Wh + go, gr < N);
            cp16(smem_u32(&BsB[((buf * 2 + 1) * BN + row) * 20 + seg * 4]), Wl + go, gr < N);
        }
        asm volatile("cp.async.commit_group;");
    };

    load_tile(0, 0);

    for (int kt = 0; kt < nt; kt++) {
        const int buf = kt & 1;
        if (kt + 1 < nt) {
            load_tile(kt + 1, buf ^ 1);
            asm volatile("cp.async.wait_group 1;");
        } else {
            asm volatile("cp.async.wait_group 0;");
        }
        __syncthreads();

        #pragma unroll
        for (int ks = 0; ks < 2; ks++) {
            const int ku = ks * 8;
            uint32_t ah[MA][4], al[MA][4], bh[NA][2], bl[NA][2];
            #pragma unroll
            for (int ma = 0; ma < MA; ma++) {
                int row = wm + ma * 16 + r4;
                const uint32_t* ph = &AsB[((buf * 2 + 0) * BM) * 20];
                ah[ma][0] = ph[row * 20 + ku + q];
                ah[ma][1] = ph[(row + 8) * 20 + ku + q];
                ah[ma][2] = ph[row * 20 + ku + 4 + q];
                ah[ma][3] = ph[(row + 8) * 20 + ku + 4 + q];
                const uint32_t* pl = &AsB[((buf * 2 + 1) * BM) * 20];
                al[ma][0] = pl[row * 20 + ku + q];
                al[ma][1] = pl[(row + 8) * 20 + ku + q];
                al[ma][2] = pl[row * 20 + ku + 4 + q];
                al[ma][3] = pl[(row + 8) * 20 + ku + 4 + q];
            }
            #pragma unroll
            for (int na = 0; na < NA; na++) {
                int col = wn + na * 8 + r4;
                const uint32_t* ph = &BsB[((buf * 2 + 0) * BN) * 20];
                bh[na][0] = ph[col * 20 + ku + q];
                bh[na][1] = ph[col * 20 + ku + 4 + q];
                const uint32_t* pl = &BsB[((buf * 2 + 1) * BN) * 20];
                bl[na][0] = pl[col * 20 + ku + q];
                bl[na][1] = pl[col * 20 + ku + 4 + q];
            }
            #define DO_MMA(AF, BF)                                                        \
                _Pragma("unroll")                                                         \
                for (int ma = 0; ma < MA; ma++)                                           \
                    _Pragma("unroll")                                                     \
                    for (int na = 0; na < NA; na++) {                                     \
                        asm volatile(                                                     \
                            "mma.sync.aligned.m16n8k16.row.col.f32.f16.f16.f32 "          \
                            "{%0,%1,%2,%3}, {%4,%5,%6,%7}, {%8,%9}, {%0,%1,%2,%3};"       \
                            : "+f"(acc[ma][na][0]), "+f"(acc[ma][na][1]),                 \
                              "+f"(acc[ma][na][2]), "+f"(acc[ma][na][3])                  \
                            : "r"(AF[ma][0]), "r"(AF[ma][1]), "r"(AF[ma][2]),             \
                              "r"(AF[ma][3]), "r"(BF[na][0]), "r"(BF[na][1]));            \
                    }
            DO_MMA(ah, bh)
            DO_MMA(ah, bl)
            DO_MMA(al, bh)
            #undef DO_MMA
        }
        __syncthreads();
    }

    #pragma unroll
    for (int ma = 0; ma < MA; ma++) {
        #pragma unroll
        for (int na = 0; na < NA; na++) {
            #pragma unroll
            for (int half = 0; half < 2; half++) {
                int r = m0 + wm + ma * 16 + r4 + half * 8;
                int c = n0 + wn + na * 8 + 2 * q;
                if (r >= M || c >= N) continue;
                float vx = acc[ma][na][half * 2 + 0];
                float vy = acc[ma][na][half * 2 + 1];
                if (MODE == 0) {
                    *(float2*)(C + (size_t)r * N + c) = make_float2(vx, vy);
                } else if (MODE == 1) {
                    float2 rv = *(const float2*)(aux + (size_t)r * N + c);
                    *(float2*)(C + (size_t)r * N + c) = make_float2(vx + rv.x, vy + rv.y);
                } else {
                    if (c < 32) {
                        *(float2*)(C + (size_t)r * 32 + c) = make_float2(vx, vy);
                    } else {
                        int dcol = c - 32;
                        C2[(size_t)r * DI + dcol]     = softplus_fast(vx + aux[dcol]);
                        C2[(size_t)r * DI + dcol + 1] = softplus_fast(vy + aux[dcol + 1]);
                    }
                }
            }
        }
    }
}

// ---------------- causal depthwise conv (taps=4) + silu + fp16 split ----------------
__global__ void conv_silu_kernel(const float* __restrict__ cw,
                                 const float* __restrict__ cb) {
    int idx = blockIdx.x * blockDim.x + threadIdx.x;
    if (idx >= NROWS * DI) return;
    int d = idx & (DI - 1);
    int row = idx >> 9;
    int l = row % SEQL;
    float acc = cb[d];
    #pragma unroll
    for (int k = 0; k < 4; k++) {
        int ls = l + k - 3;
        if (ls >= 0)
            acc = fmaf(g_xz[(size_t)(row + k - 3) * (2 * DI) + d], cw[d * 4 + k], acc);
    }
    float v = siluf(acc);
    g_u[idx] = v;
    __half hi, lo;
    split_h(v, hi, lo);
    g_uh[idx] = hi;
    g_ul[idx] = lo;
}

// ---------------- scan pass 1: local chunk scan ----------------
__global__ void __launch_bounds__(128) scan1_kernel(const float* __restrict__ A_log) {
    const int tid = threadIdx.x;
    const int g = tid >> 4, n = tid & 15;
    int bi = blockIdx.x;
    const int b = bi / (NCH * 64);
    const int r = bi % (NCH * 64);
    const int ch = r >> 6;
    const int grp = r & 63;
    const int d = grp * 8 + g;
    const float a = -__expf(A_log[d * DS + n]);
    const int rowbase = b * SEQL + ch * CL;

    float h = 0.f, pe = 1.f;
    float pdt[8], pu[8], pB[8], pC[8];
    #pragma unroll
    for (int i = 0; i < 8; i++) {
        int base = rowbase + i;
        pdt[i] = g_dt[(size_t)base * DI + d];
        pu[i]  = g_u[(size_t)base * DI + d];
        pB[i]  = g_bc[base * 32 + n];
        pC[i]  = g_bc[base * 32 + 16 + n];
    }
    for (int tb = 0; tb < CL; tb += 8) {
        float cdt[8], cu[8], cB[8], cC[8];
        #pragma unroll
        for (int i = 0; i < 8; i++) {
            cdt[i] = pdt[i]; cu[i] = pu[i]; cB[i] = pB[i]; cC[i] = pC[i];
        }
        if (tb + 8 < CL) {
            #pragma unroll
            for (int i = 0; i < 8; i++) {
                int base = rowbase + tb + 8 + i;
                pdt[i] = g_dt[(size_t)base * DI + d];
                pu[i]  = g_u[(size_t)base * DI + d];
                pB[i]  = g_bc[base * 32 + n];
                pC[i]  = g_bc[base * 32 + 16 + n];
            }
        }
        float e[8], duB[8];
        #pragma unroll
        for (int i = 0; i < 8; i++) {
            e[i]   = __expf(cdt[i] * a);
            duB[i] = cdt[i] * cu[i] * cB[i];
        }
        float part[8];
        #pragma unroll
        for (int i = 0; i < 8; i++) {
            h = fmaf(e[i], h, duB[i]);
            pe *= e[i];
            part[i] = h * cC[i];
        }
        #pragma unroll
        for (int off = 8; off; off >>= 1)
            #pragma unroll
            for (int i = 0; i < 8; i++)
                part[i] += __shfl_xor_sync(0xffffffffu, part[i], off, 16);
        if (n == 0) {
            #pragma unroll
            for (int i = 0; i < 8; i++)
                g_yp[(size_t)(rowbase + tb + i) * DI + d] = part[i];
        }
    }
    int s = ((b * NCH + ch) * DI + d) * DS + n;
    g_pe[s] = pe;
    g_he[s] = h;
}

// ---------------- scan mid: chain chunk states ----------------
__global__ void scanmid_kernel() {
    int idx = blockIdx.x * blockDim.x + threadIdx.x;
    if (idx >= BATCH * DI * DS) return;
    int b = idx / (DI * DS);
    int dn = idx % (DI * DS);
    float h = 0.f;
    for (int ch = 0; ch < NCH; ch++) {
        int s = (b * NCH + ch) * DI * DS + dn;
        g_h0[s] = h;
        h = g_pe[s] * h + g_he[s];
    }
}

// ---------------- scan pass 2: correction + gating ----------------
__global__ void __launch_bounds__(128) scan2_kernel(const float* __restrict__ A_log,
                                                    const float* __restrict__ Dvec) {
    const int tid = threadIdx.x;
    const int g = tid >> 4, n = tid & 15;
    int bi = blockIdx.x;
    const int b = bi / (NCH * 64);
    const int r = bi % (NCH * 64);
    const int ch = r >> 6;
    const int grp = r & 63;
    const int d = grp * 8 + g;
    const float a = -__expf(A_log[d * DS + n]);
    const float Dv = Dvec[d];
    const int rowbase = b * SEQL + ch * CL;

    float P = g_h0[((b * NCH + ch) * DI + d) * DS + n];

    float pdt[8], pu[8], pz[8], pC[8], pyp[8];
    #pragma unroll
    for (int i = 0; i < 8; i++) {
        int base = rowbase + i;
        pdt[i] = g_dt[(size_t)base * DI + d];
        pu[i]  = g_u[(size_t)base * DI + d];
        pz[i]  = g_xz[(size_t)base * (2 * DI) + DI + d];
        pC[i]  = g_bc[base * 32 + 16 + n];
        pyp[i] = g_yp[(size_t)base * DI + d];
    }
    for (int tb = 0; tb < CL; tb += 8) {
        float cdt[8], cu[8], cz[8], cC[8], cyp[8];
        #pragma unroll
        for (int i = 0; i < 8; i++) {
            cdt[i] = pdt[i]; cu[i] = pu[i]; cz[i] = pz[i]; cC[i] = pC[i]; cyp[i] = pyp[i];
        }
        if (tb + 8 < CL) {
            #pragma unroll
            for (int i = 0; i < 8; i++) {
                int base = rowbase + tb + 8 + i;
                pdt[i] = g_dt[(size_t)base * DI + d];
                pu[i]  = g_u[(size_t)base * DI + d];
                pz[i]  = g_xz[(size_t)base * (2 * DI) + DI + d];
                pC[i]  = g_bc[base * 32 + 16 + n];
                pyp[i] = g_yp[(size_t)base * DI + d];
            }
        }
        float c[8];
        #pragma unroll
        for (int i = 0; i < 8; i++) {
            P *= __expf(cdt[i] * a);
            c[i] = cC[i] * P;
        }
        #pragma unroll
        for (int off = 8; off; off >>= 1)
            #pragma unroll
            for (int i = 0; i < 8; i++)
                c[i] += __shfl_xor_sync(0xffffffffu, c[i], off, 16);
        if (n == 0) {
            #pragma unroll
            for (int i = 0; i < 8; i++) {
                float y = cyp[i] + c[i] + cu[i] * Dv;
                float v = y * siluf(cz[i]);
                __half hi, lo;
                split_h(v, hi, lo);
                size_t o = (size_t)(rowbase + tb + i) * DI + d;
                g_yh[o] = hi;
                g_yl[o] = lo;
            }
        }
    }
}

// ---------------- head: warp per row ----------------
__global__ void __launch_bounds__(256) head_kernel(const float* __restrict__ hw,
                                                   const float* __restrict__ hb,
                                                   float* __restrict__ out) {
    int warp = threadIdx.x >> 5, lane = threadIdx.x & 31;
    int row = blockIdx.x * 8 + warp;
    if (row >= NROWS) return;
    const float* xr = g_ln + (size_t)row * DM + lane * 8;
    float4 v0 = *(const float4*)xr;
    float4 v1 = *(const float4*)(xr + 4);
    float4 w0 = *(const float4*)(hw + lane * 8);
    float4 w1 = *(const float4*)(hw + lane * 8 + 4);
    float s = v0.x * w0.x + v0.y * w0.y + v0.z * w0.z + v0.w * w0.w
            + v1.x * w1.x + v1.y * w1.y + v1.z * w1.z + v1.w * w1.w;
    #pragma unroll
    for (int o = 16; o > 0; o >>= 1) s += __shfl_xor_sync(0xffffffffu, s, o);
    if (lane == 0) out[row] = s + hb[0];
}

// ---------------- host orchestration ----------------
extern "C" void kernel_launch(void* const* d_in, const int* in_sizes, int n_in,
                              void* d_out, int out_size) {
    const float* x    = (const float*)d_in[0];
    const float* bw   = (const float*)d_in[1];
    const float* bb   = (const float*)d_in[2];
    const float* ge   = (const float*)d_in[3];
    const float* me   = (const float*)d_in[4];
    const float* lnw  = (const float*)d_in[5];
    const float* lnb  = (const float*)d_in[6];
    const float* ipw  = (const float*)d_in[7];
    const float* cw   = (const float*)d_in[8];
    const float* cb   = (const float*)d_in[9];
    const float* xpw  = (const float*)d_in[10];
    const float* dtw  = (const float*)d_in[11];
    const float* dtb  = (const float*)d_in[12];
    const float* alog = (const float*)d_in[13];
    const float* Dv   = (const float*)d_in[14];
    const float* opw  = (const float*)d_in[15];
    const float* fw   = (const float*)d_in[16];
    const float* fb   = (const float*)d_in[17];
    const float* hw   = (const float*)d_in[18];
    const float* hb   = (const float*)d_in[19];
    float* out = (float*)d_out;

    float *p_h, *p_ln, *p_xz, *p_bc, *p_dt;
    __half *p_lnh, *p_lnl, *p_uh, *p_ul, *p_yh, *p_yl;
    __half *p_wih, *p_wil, *p_wbh, *p_wbl, *p_woh, *p_wol;
    cudaGetSymbolAddress((void**)&p_h, g_h);
    cudaGetSymbolAddress((void**)&p_ln, g_ln);
    cudaGetSymbolAddress((void**)&p_xz, g_xz);
    cudaGetSymbolAddress((void**)&p_bc, g_bc);
    cudaGetSymbolAddress((void**)&p_dt, g_dt);
    cudaGetSymbolAddress((void**)&p_lnh, g_lnh);
    cudaGetSymbolAddress((void**)&p_lnl, g_lnl);
    cudaGetSymbolAddress((void**)&p_uh, g_uh);
    cudaGetSymbolAddress((void**)&p_ul, g_ul);
    cudaGetSymbolAddress((void**)&p_yh, g_yh);
    cudaGetSymbolAddress((void**)&p_yl, g_yl);
    cudaGetSymbolAddress((void**)&p_wih, g_wih);
    cudaGetSymbolAddress((void**)&p_wil, g_wil);
    cudaGetSymbolAddress((void**)&p_wbh, g_wbh);
    cudaGetSymbolAddress((void**)&p_wbl, g_wbl);
    cudaGetSymbolAddress((void**)&p_woh, g_woh);
    cudaGetSymbolAddress((void**)&p_wol, g_wol);

    const int SM_IN  = (4 * 128 * 20 + 4 * 64 * 20) * 4;   // 61440
    const int SM_X   = (4 * 64 * 20 + 4 * 128 * 20) * 4;   // 61440
    const int SM_OUT = (4 * 64 * 20 + 4 * 128 * 20) * 4;   // 61440
    cudaFuncSetAttribute(gemm_sp<128, 64, 4, 2, 0>,
                         cudaFuncAttributeMaxDynamicSharedMemorySize, SM_IN);
    cudaFuncSetAttribute(gemm_sp<64, 128, 2, 4, 2>,
                         cudaFuncAttributeMaxDynamicSharedMemorySize, SM_X);
    cudaFuncSetAttribute(gemm_sp<64, 128, 2, 4, 1>,
                         cudaFuncAttributeMaxDynamicSharedMemorySize, SM_OUT);

    // launch 1
    embed_kernel<<<(NROWS * DM + 255) / 256, 256>>>(x, bw, bb, ge, me);
    // launch 2
    wsplit_kernel<<<(4 * 1024 * DM + 255) / 256, 256>>>(ipw, p_wih, p_wil, 4 * 1024 * DM);

    const int SCAN_GRID = BATCH * NCH * 64;   // 3200

    for (int i = 0; i < 4; i++) {
        // launch 3 (i=0)
        ln_kernel<<<(NROWS + 7) / 8, 256>>>(p_h, lnw + i * DM, lnb + i * DM,
                                            nullptr, p_lnh, p_lnl);
        {   // launch 4 (i=0): in_proj — profiled slot
            dim3 grid(1024 / 64, (NROWS + 127) / 128);
            gemm_sp<128, 64, 4, 2, 0><<<grid, 256, SM_IN>>>(
                p_lnh, p_lnl, p_wih + (size_t)i * 1024 * DM, p_wil + (size_t)i * 1024 * DM,
                p_xz, nullptr, nullptr, NROWS, 1024, DM);
        }
        if (i == 0) {
            wbig_kernel<<<4 * NBIG, 256>>>(xpw, dtw);
            wsplit_kernel<<<(4 * DM * DI + 255) / 256, 256>>>(opw, p_woh, p_wol, 4 * DM * DI);
        }
        conv_silu_kernel<<<(NROWS * DI + 255) / 256, 256>>>(cw + i * DI * 4, cb + i * DI);
        {   // x_proj + dt fused: M=4000, N=544, K=512
            dim3 grid((NBIG + 127) / 128, (NROWS + 63) / 64);
            gemm_sp<64, 128, 2, 4, 2><<<grid, 256, SM_X>>>(
                p_uh, p_ul, p_wbh + (size_t)i * NBIG * DI, p_wbl + (size_t)i * NBIG * DI,
                p_bc, dtb + i * DI, p_dt, NROWS, NBIG, DI);
        }
        scan1_kernel<<<SCAN_GRID, 128>>>(alog + (size_t)i * DI * DS);
        scanmid_kernel<<<(BATCH * DI * DS + 255) / 256, 256>>>();
        scan2_kernel<<<SCAN_GRID, 128>>>(alog + (size_t)i * DI * DS, Dv + i * DI);
        {   // out_proj + residual
            dim3 grid(256 / 128, (NROWS + 63) / 64);
            gemm_sp<64, 128, 2, 4, 1><<<grid, 256, SM_OUT>>>(
                p_yh, p_yl, p_woh + (size_t)i * DM * DI, p_wol + (size_t)i * DM * DI,
                p_h, p_h, nullptr, NROWS, 256, DI);
        }
    }

    ln_kernel<<<(NROWS + 7) / 8, 256>>>(p_h, fw, fb, p_ln, nullptr, nullptr);
    head_kernel<<<(NROWS + 7) / 8, 256>>>(hw, hb, out);
}

// round 8
// speedup vs baseline: 2.7331x; 1.0633x over previous
#include <cuda_runtime.h>
#include <cuda_fp16.h>
#include <math.h>
#include <stdint.h>

#define BATCH 2
#define SEQL 2000
#define DM 256
#define DI 512
#define DS 16
#define RNK 16
#define NROWS (BATCH*SEQL)   // 4000
#define NCH 25               // scan chunks
#define CL 80                // chunk length
#define NBIG 544             // 32 (B|C) + 512 (dt)

// ---------------- scratch (device globals; no allocations) ----------------
__device__ float g_h[NROWS*DM];      // residual stream
__device__ float g_ln[NROWS*DM];     // final layernorm out
__device__ float g_xz[NROWS*2*DI];   // in_proj output (u | z)
__device__ float g_u[NROWS*DI];      // conv+silu output fp32
__device__ float g_bc[NROWS*32];     // x_proj B|C compact
__device__ float g_dt[NROWS*DI];     // softplus(dt)
__device__ float g_yp[NROWS*DI];     // scan pass1 partial y
__device__ float g_pe[BATCH*NCH*DI*DS];
__device__ float g_he[BATCH*NCH*DI*DS];

// fp16 hi/lo split operands
__device__ __align__(16) __half g_lnh[NROWS*DM], g_lnl[NROWS*DM];
__device__ __align__(16) __half g_uh [NROWS*DI], g_ul [NROWS*DI];
__device__ __align__(16) __half g_yh [NROWS*DI], g_yl [NROWS*DI];
__device__ __align__(16) __half g_wih[(size_t)4*1024*DM], g_wil[(size_t)4*1024*DM];
__device__ __align__(16) __half g_wbh[(size_t)4*NBIG*DI], g_wbl[(size_t)4*NBIG*DI];
__device__ __align__(16) __half g_woh[(size_t)4*DM*DI],   g_wol[(size_t)4*DM*DI];

// ---------------- helpers ----------------
__device__ __forceinline__ float siluf(float x) {
    return x * __frcp_rn(1.f + __expf(-x));
}
__device__ __forceinline__ float softplus_fast(float x) {
    return fmaxf(x, 0.f) + __logf(1.f + __expf(-fabsf(x)));
}
__device__ __forceinline__ void split_h(float v, __half& hi, __half& lo) {
    hi = __float2half(v);
    lo = __float2half(v - __half2float(hi));
}
__device__ __forceinline__ uint32_t smem_u32(const void* p) {
    uint32_t a;
    asm("{ .reg .u64 t; cvta.to.shared.u64 t, %1; cvt.u32.u64 %0, t; }" : "=r"(a) : "l"(p));
    return a;
}
__device__ __forceinline__ void cp16(uint32_t dst, const void* src, bool valid) {
    int sz = valid ? 16 : 0;
    asm volatile("cp.async.ca.shared.global [%0], [%1], 16, %2;"
                 :: "r"(dst), "l"(src), "r"(sz));
}

// ---------------- embed ----------------
__global__ void embed_kernel(const float* __restrict__ x,
                             const float* __restrict__ bw,
                             const float* __restrict__ bb,
                             const float* __restrict__ ge,
                             const float* __restrict__ me) {
    int idx = blockIdx.x * blockDim.x + threadIdx.x;
    if (idx >= NROWS * DM) return;
    int d = idx & (DM - 1);
    int row = idx >> 8;
    int l = row % SEQL;
    g_h[idx] = x[row] * bw[d] + bb[d] + ge[l * DM + d] + me[d];
}

// ---------------- weight split fp32 -> (fp16 hi, lo) ----------------
__global__ void wsplit_kernel(const float* __restrict__ W,
                              __half* __restrict__ Wh, __half* __restrict__ Wl, int n) {
    int idx = blockIdx.x * blockDim.x + threadIdx.x;
    if (idx >= n) return;
    __half hi, lo;
    split_h(W[idx], hi, lo);
    Wh[idx] = hi; Wl[idx] = lo;
}

// ---------------- build W_big = [xp_w rows 16..47 | dt_w @ xp_w rows 0..15] ----------------
__global__ void wbig_kernel(const float* __restrict__ xpw,
                            const float* __restrict__ dtpw) {
    int bid = blockIdx.x;            // l*NBIG + j
    int l = bid / NBIG, j = bid % NBIG;
    int t = threadIdx.x;
    __shared__ float s[RNK];
    const float* xp = xpw + (size_t)l * 48 * DI;
    size_t obase = ((size_t)l * NBIG + j) * DI;
    if (j < 32) {
        for (int k = t; k < DI; k += 256) {
            __half hi, lo;
            split_h(xp[(16 + j) * DI + k], hi, lo);
            g_wbh[obase + k] = hi; g_wbl[obase + k] = lo;
        }
    } else {
        int d = j - 32;
        if (t < RNK) s[t] = dtpw[((size_t)l * DI + d) * RNK + t];
        __syncthreads();
        for (int k = t; k < DI; k += 256) {
            float acc = 0.f;
            #pragma unroll
            for (int r = 0; r < RNK; r++)
                acc = fmaf(s[r], xp[r * DI + k], acc);
            __half hi, lo;
            split_h(acc, hi, lo);
            g_wbh[obase + k] = hi; g_wbl[obase + k] = lo;
        }
    }
}

// ---------------- layernorm: warp per row ----------------
__global__ void __launch_bounds__(256) ln_kernel(const float* __restrict__ X,
                                                 const float* __restrict__ w,
                                                 const float* __restrict__ b,
                                                 float* __restrict__ Y,
                                                 __half* __restrict__ Yh,
                                                 __half* __restrict__ Yl) {
    int warp = threadIdx.x >> 5, lane = threadIdx.x & 31;
    int row = blockIdx.x * 8 + warp;
    if (row >= NROWS) return;
    const float* xr = X + (size_t)row * DM + lane * 8;
    float4 v0 = *(const float4*)xr;
    float4 v1 = *(const float4*)(xr + 4);
    float va[8] = {v0.x, v0.y, v0.z, v0.w, v1.x, v1.y, v1.z, v1.w};
    float s1 = 0.f, s2 = 0.f;
    #pragma unroll
    for (int i = 0; i < 8; i++) { s1 += va[i]; s2 += va[i] * va[i]; }
    #pragma unroll
    for (int o = 16; o > 0; o >>= 1) {
        s1 += __shfl_xor_sync(0xffffffffu, s1, o);
        s2 += __shfl_xor_sync(0xffffffffu, s2, o);
    }
    float mu = s1 * (1.f / DM);
    float var = s2 * (1.f / DM) - mu * mu;
    float rs = rsqrtf(var + 1e-5f);
    float4 w0 = *(const float4*)(w + lane * 8);
    float4 w1 = *(const float4*)(w + lane * 8 + 4);
    float4 b0 = *(const float4*)(b + lane * 8);
    float4 b1 = *(const float4*)(b + lane * 8 + 4);
    float wa[8] = {w0.x, w0.y, w0.z, w0.w, w1.x, w1.y, w1.z, w1.w};
    float ba[8] = {b0.x, b0.y, b0.z, b0.w, b1.x, b1.y, b1.z, b1.w};
    float oa[8];
    #pragma unroll
    for (int i = 0; i < 8; i++) oa[i] = (va[i] - mu) * rs * wa[i] + ba[i];
    if (Y) {
        float* yr = Y + (size_t)row * DM + lane * 8;
        *(float4*)yr = make_float4(oa[0], oa[1], oa[2], oa[3]);
        *(float4*)(yr + 4) = make_float4(oa[4], oa[5], oa[6], oa[7]);
    }
    if (Yh) {
        __half hh[8], ll[8];
        #pragma unroll
        for (int i = 0; i < 8; i++) split_h(oa[i], hh[i], ll[i]);
        *(uint4*)(Yh + (size_t)row * DM + lane * 8) = *(uint4*)hh;
        *(uint4*)(Yl + (size_t)row * DM + lane * 8) = *(uint4*)ll;
    }
}

// ---------------- split fp16 tensor GEMM, 3-term ----------------
// MODE 0: plain store. MODE 1: += res. MODE 2: col<32 -> BC; col>=32 -> softplus -> DT.
template<int BM, int BN, int WMG, int WNG, int MODE>
__global__ void __launch_bounds__(256) gemm_sp(const __half* __restrict__ Ah,
                                               const __half* __restrict__ Al,
                                               const __half* __restrict__ Wh,
                                               const __half* __restrict__ Wl,
                                               float* __restrict__ C,
                                               const float* __restrict__ aux,
                                               float* __restrict__ C2,
                                               int M, int N, int K) {
    constexpr int MA = BM / (WMG * 16);
    constexpr int NA = BN / (WNG * 8);
    constexpr int ACH = BM * 4 / 256;
    constexpr int BCH = BN * 4 / 256;

    extern __shared__ uint32_t dynsm[];
    uint32_t* AsB = dynsm;                 // [2][2][BM][20]
    uint32_t* BsB = dynsm + 4 * BM * 20;   // [2][2][BN][20]

    const int t = threadIdx.x;
    const int lane = t & 31, warp = t >> 5;
    const int r4 = lane >> 2, q = lane & 3;
    const int mi = warp / WNG, ni = warp % WNG;
    const int wm = mi * (BM / WMG), wn = ni * (BN / WNG);
    const int m0 = blockIdx.y * BM, n0 = blockIdx.x * BN;

    float acc[MA][NA][4];
    #pragma unroll
    for (int i = 0; i < MA; i++)
        #pragma unroll
        for (int j = 0; j < NA; j++)
            #pragma unroll
            for (int k = 0; k < 4; k++) acc[i][j][k] = 0.f;

    const int nt = K >> 5;

    auto load_tile = [&](int kt, int buf) {
        #pragma unroll
        for (int j = 0; j < ACH; j++) {
            int id = t + j * 256;
            int row = id >> 2, seg = id & 3;
            int gr = m0 + row;
            size_t go = (size_t)gr * K + kt * 32 + seg * 8;
            cp16(smem_u32(&AsB[((buf * 2 + 0) * BM + row) * 20 + seg * 4]), Ah + go, gr < M);
            cp16(smem_u32(&AsB[((buf * 2 + 1) * BM + row) * 20 + seg * 4]), Al + go, gr < M);
        }
        #pragma unroll
        for (int j = 0; j < BCH; j++) {
            int id = t + j * 256;
            int row = id >> 2, seg = id & 3;
            int gr = n0 + row;
            size_t go = (size_t)gr * K + kt * 32 + seg * 8;
            cp16(smem_u32(&BsB[((buf * 2 + 0) * BN + row) * 20 + seg * 4]), Wh + go, gr < N);
            cp16(smem_u32(&BsB[((buf * 2 + 1) * BN + row) * 20 + seg * 4]), Wl + go, gr < N);
        }
        asm volatile("cp.async.commit_group;");
    };

    load_tile(0, 0);

    for (int kt = 0; kt < nt; kt++) {
        const int buf = kt & 1;
        if (kt + 1 < nt) {
            load_tile(kt + 1, buf ^ 1);
            asm volatile("cp.async.wait_group 1;");
        } else {
            asm volatile("cp.async.wait_group 0;");
        }
        __syncthreads();

        #pragma unroll
        for (int ks = 0; ks < 2; ks++) {
            const int ku = ks * 8;
            uint32_t ah[MA][4], al[MA][4], bh[NA][2], bl[NA][2];
            #pragma unroll
            for (int ma = 0; ma < MA; ma++) {
                int row = wm + ma * 16 + r4;
                const uint32_t* ph = &AsB[((buf * 2 + 0) * BM) * 20];
                ah[ma][0] = ph[row * 20 + ku + q];
                ah[ma][1] = ph[(row + 8) * 20 + ku + q];
                ah[ma][2] = ph[row * 20 + ku + 4 + q];
                ah[ma][3] = ph[(row + 8) * 20 + ku + 4 + q];
                const uint32_t* pl = &AsB[((buf * 2 + 1) * BM) * 20];
                al[ma][0] = pl[row * 20 + ku + q];
                al[ma][1] = pl[(row + 8) * 20 + ku + q];
                al[ma][2] = pl[row * 20 + ku + 4 + q];
                al[ma][3] = pl[(row + 8) * 20 + ku + 4 + q];
            }
            #pragma unroll
            for (int na = 0; na < NA; na++) {
                int col = wn + na * 8 + r4;
                const uint32_t* ph = &BsB[((buf * 2 + 0) * BN) * 20];
                bh[na][0] = ph[col * 20 + ku + q];
                bh[na][1] = ph[col * 20 + ku + 4 + q];
                const uint32_t* pl = &BsB[((buf * 2 + 1) * BN) * 20];
                bl[na][0] = pl[col * 20 + ku + q];
                bl[na][1] = pl[col * 20 + ku + 4 + q];
            }
            #define DO_MMA(AF, BF)                                                        \
                _Pragma("unroll")                                                         \
                for (int ma = 0; ma < MA; ma++)                                           \
                    _Pragma("unroll")                                                     \
                    for (int na = 0; na < NA; na++) {                                     \
                        asm volatile(                                                     \
                            "mma.sync.aligned.m16n8k16.row.col.f32.f16.f16.f32 "          \
                            "{%0,%1,%2,%3}, {%4,%5,%6,%7}, {%8,%9}, {%0,%1,%2,%3};"       \
                            : "+f"(acc[ma][na][0]), "+f"(acc[ma][na][1]),                 \
                              "+f"(acc[ma][na][2]), "+f"(acc[ma][na][3])                  \
                            : "r"(AF[ma][0]), "r"(AF[ma][1]), "r"(AF[ma][2]),             \
                              "r"(AF[ma][3]), "r"(BF[na][0]), "r"(BF[na][1]));            \
                    }
            DO_MMA(ah, bh)
            DO_MMA(ah, bl)
            DO_MMA(al, bh)
            #undef DO_MMA
        }
        __syncthreads();
    }

    #pragma unroll
    for (int ma = 0; ma < MA; ma++) {
        #pragma unroll
        for (int na = 0; na < NA; na++) {
            #pragma unroll
            for (int half = 0; half < 2; half++) {
                int r = m0 + wm + ma * 16 + r4 + half * 8;
                int c = n0 + wn + na * 8 + 2 * q;
                if (r >= M || c >= N) continue;
                float vx = acc[ma][na][half * 2 + 0];
                float vy = acc[ma][na][half * 2 + 1];
                if (MODE == 0) {
                    *(float2*)(C + (size_t)r * N + c) = make_float2(vx, vy);
                } else if (MODE == 1) {
                    float2 rv = *(const float2*)(aux + (size_t)r * N + c);
                    *(float2*)(C + (size_t)r * N + c) = make_float2(vx + rv.x, vy + rv.y);
                } else {
                    if (c < 32) {
                        *(float2*)(C + (size_t)r * 32 + c) = make_float2(vx, vy);
                    } else {
                        int dcol = c - 32;
                        C2[(size_t)r * DI + dcol]     = softplus_fast(vx + aux[dcol]);
                        C2[(size_t)r * DI + dcol + 1] = softplus_fast(vy + aux[dcol + 1]);
                    }
                }
            }
        }
    }
}

// ---------------- causal depthwise conv (taps=4) + silu + fp16 split ----------------
__global__ void conv_silu_kernel(const float* __restrict__ cw,
                                 const float* __restrict__ cb) {
    int idx = blockIdx.x * blockDim.x + threadIdx.x;
    if (idx >= NROWS * DI) return;
    int d = idx & (DI - 1);
    int row = idx >> 9;
    int l = row % SEQL;
    float acc = cb[d];
    #pragma unroll
    for (int k = 0; k < 4; k++) {
        int ls = l + k - 3;
        if (ls >= 0)
            acc = fmaf(g_xz[(size_t)(row + k - 3) * (2 * DI) + d], cw[d * 4 + k], acc);
    }
    float v = siluf(acc);
    g_u[idx] = v;
    __half hi, lo;
    split_h(v, hi, lo);
    g_uh[idx] = hi;
    g_ul[idx] = lo;
}

// ---------------- scan pass 1: local chunk scan (B/C in smem, lean regs) ----------------
__global__ void __launch_bounds__(128) scan1_kernel(const float* __restrict__ A_log) {
    __shared__ float sB[CL][DS];
    __shared__ float sC[CL][DS];
    const int tid = threadIdx.x;
    const int g = tid >> 4, n = tid & 15;
    const int bi = blockIdx.x;
    const int b = bi / (NCH * 64);
    const int r = bi % (NCH * 64);
    const int ch = r >> 6;
    const int d = (r & 63) * 8 + g;
    const int rowbase = b * SEQL + ch * CL;

    // cooperative stage of B|C rows: CL*32 floats, float4 per thread
    for (int i = tid; i < CL * 8; i += 128) {
        int tt = i >> 3, j4 = (i & 7) * 4;
        float4 v = *(const float4*)(g_bc + (size_t)(rowbase + tt) * 32 + j4);
        float* dst = (j4 < 16) ? &sB[tt][j4] : &sC[tt][j4 - 16];
        dst[0] = v.x; dst[1] = v.y; dst[2] = v.z; dst[3] = v.w;
    }
    const float a = -__expf(A_log[d * DS + n]);
    __syncthreads();

    float h = 0.f, pe = 1.f;
    for (int tb = 0; tb < CL; tb += 8) {
        float dt[8], u[8];
        #pragma unroll
        for (int i = 0; i < 8; i++) {
            size_t o = (size_t)(rowbase + tb + i) * DI + d;
            dt[i] = g_dt[o];
            u[i]  = g_u[o];
        }
        float e[8], duB[8];
        #pragma unroll
        for (int i = 0; i < 8; i++) {
            e[i]   = __expf(dt[i] * a);
            duB[i] = dt[i] * u[i] * sB[tb + i][n];
        }
        float part[8];
        #pragma unroll
        for (int i = 0; i < 8; i++) {
            h = fmaf(e[i], h, duB[i]);
            pe *= e[i];
            part[i] = h * sC[tb + i][n];
        }
        #pragma unroll
        for (int off = 8; off; off >>= 1)
            #pragma unroll
            for (int i = 0; i < 8; i++)
                part[i] += __shfl_xor_sync(0xffffffffu, part[i], off, 16);
        // after allreduce every lane holds all 8 sums; lanes n<8 write one each
        if (n < 8)
            g_yp[(size_t)(rowbase + tb + n) * DI + d] = part[n];
    }
    int s = ((b * NCH + ch) * DI + d) * DS + n;
    g_pe[s] = pe;
    g_he[s] = h;
}

// ---------------- scan pass 2: h0 prefix + correction + gating ----------------
__global__ void __launch_bounds__(128) scan2_kernel(const float* __restrict__ A_log,
                                                    const float* __restrict__ Dvec) {
    __shared__ float sC[CL][DS];
    const int tid = threadIdx.x;
    const int g = tid >> 4, n = tid & 15;
    const int bi = blockIdx.x;
    const int b = bi / (NCH * 64);
    const int r = bi % (NCH * 64);
    const int ch = r >> 6;
    const int d = (r & 63) * 8 + g;
    const int rowbase = b * SEQL + ch * CL;

    // stage C rows
    for (int i = tid; i < CL * 4; i += 128) {
        int tt = i >> 2, j4 = (i & 3) * 4;
        float4 v = *(const float4*)(g_bc + (size_t)(rowbase + tt) * 32 + 16 + j4);
        sC[tt][j4] = v.x; sC[tt][j4 + 1] = v.y; sC[tt][j4 + 2] = v.z; sC[tt][j4 + 3] = v.w;
    }
    const float a = -__expf(A_log[d * DS + n]);
    const float Dv = Dvec[d];

    // h0 prefix: chain pe/he over prior chunks (loads independent -> MLP)
    float P = 0.f;
    {
        int sbase = (b * NCH * DI + d) * DS + n;
        for (int c2 = 0; c2 < ch; c2++) {
            int s = sbase + c2 * DI * DS;
            P = g_pe[s] * P + g_he[s];
        }
    }
    __syncthreads();

    for (int tb = 0; tb < CL; tb += 8) {
        float dt[8], u[8], z[8], yp[8];
        #pragma unroll
        for (int i = 0; i < 8; i++) {
            size_t o = (size_t)(rowbase + tb + i) * DI + d;
            dt[i] = g_dt[o];
            u[i]  = g_u[o];
            z[i]  = g_xz[(size_t)(rowbase + tb + i) * (2 * DI) + DI + d];
            yp[i] = g_yp[o];
        }
        float c[8];
        #pragma unroll
        for (int i = 0; i < 8; i++) {
            P *= __expf(dt[i] * a);
            c[i] = sC[tb + i][n] * P;
        }
        #pragma unroll
        for (int off = 8; off; off >>= 1)
            #pragma unroll
            for (int i = 0; i < 8; i++)
                c[i] += __shfl_xor_sync(0xffffffffu, c[i], off, 16);
        if (n < 8) {
            float y = yp[n] + c[n] + u[n] * Dv;
            float v = y * siluf(z[n]);
            __half hi, lo;
            split_h(v, hi, lo);
            size_t o = (size_t)(rowbase + tb + n) * DI + d;
            g_yh[o] = hi;
            g_yl[o] = lo;
        }
    }
}

// ---------------- head: warp per row ----------------
__global__ void __launch_bounds__(256) head_kernel(const float* __restrict__ hw,
                                                   const float* __restrict__ hb,
                                                   float* __restrict__ out) {
    int warp = threadIdx.x >> 5, lane = threadIdx.x & 31;
    int row = blockIdx.x * 8 + warp;
    if (row >= NROWS) return;
    const float* xr = g_ln + (size_t)row * DM + lane * 8;
    float4 v0 = *(const float4*)xr;
    float4 v1 = *(const float4*)(xr + 4);
    float4 w0 = *(const float4*)(hw + lane * 8);
    float4 w1 = *(const float4*)(hw + lane * 8 + 4);
    float s = v0.x * w0.x + v0.y * w0.y + v0.z * w0.z + v0.w * w0.w
            + v1.x * w1.x + v1.y * w1.y + v1.z * w1.z + v1.w * w1.w;
    #pragma unroll
    for (int o = 16; o > 0; o >>= 1) s += __shfl_xor_sync(0xffffffffu, s, o);
    if (lane == 0) out[row] = s + hb[0];
}

// ---------------- host orchestration ----------------
extern "C" void kernel_launch(void* const* d_in, const int* in_sizes, int n_in,
                              void* d_out, int out_size) {
    const float* x    = (const float*)d_in[0];
    const float* bw   = (const float*)d_in[1];
    const float* bb   = (const float*)d_in[2];
    const float* ge   = (const float*)d_in[3];
    const float* me   = (const float*)d_in[4];
    const float* lnw  = (const float*)d_in[5];
    const float* lnb  = (const float*)d_in[6];
    const float* ipw  = (const float*)d_in[7];
    const float* cw   = (const float*)d_in[8];
    const float* cb   = (const float*)d_in[9];
    const float* xpw  = (const float*)d_in[10];
    const float* dtw  = (const float*)d_in[11];
    const float* dtb  = (const float*)d_in[12];
    const float* alog = (const float*)d_in[13];
    const float* Dv   = (const float*)d_in[14];
    const float* opw  = (const float*)d_in[15];
    const float* fw   = (const float*)d_in[16];
    const float* fb   = (const float*)d_in[17];
    const float* hw   = (const float*)d_in[18];
    const float* hb   = (const float*)d_in[19];
    float* out = (float*)d_out;

    float *p_h, *p_ln, *p_xz, *p_bc, *p_dt;
    __half *p_lnh, *p_lnl, *p_uh, *p_ul, *p_yh, *p_yl;
    __half *p_wih, *p_wil, *p_wbh, *p_wbl, *p_woh, *p_wol;
    cudaGetSymbolAddress((void**)&p_h, g_h);
    cudaGetSymbolAddress((void**)&p_ln, g_ln);
    cudaGetSymbolAddress((void**)&p_xz, g_xz);
    cudaGetSymbolAddress((void**)&p_bc, g_bc);
    cudaGetSymbolAddress((void**)&p_dt, g_dt);
    cudaGetSymbolAddress((void**)&p_lnh, g_lnh);
    cudaGetSymbolAddress((void**)&p_lnl, g_lnl);
    cudaGetSymbolAddress((void**)&p_uh, g_uh);
    cudaGetSymbolAddress((void**)&p_ul, g_ul);
    cudaGetSymbolAddress((void**)&p_yh, g_yh);
    cudaGetSymbolAddress((void**)&p_yl, g_yl);
    cudaGetSymbolAddress((void**)&p_wih, g_wih);
    cudaGetSymbolAddress((void**)&p_wil, g_wil);
    cudaGetSymbolAddress((void**)&p_wbh, g_wbh);
    cudaGetSymbolAddress((void**)&p_wbl, g_wbl);
    cudaGetSymbolAddress((void**)&p_woh, g_woh);
    cudaGetSymbolAddress((void**)&p_wol, g_wol);

    const int SM_IN  = (4 * 128 * 20 + 4 * 128 * 20) * 4;  // 81920
    const int SM_X   = (4 * 64 * 20 + 4 * 128 * 20) * 4;   // 61440
    const int SM_OUT = (4 * 64 * 20 + 4 * 128 * 20) * 4;   // 61440
    cudaFuncSetAttribute(gemm_sp<128, 128, 2, 4, 0>,
                         cudaFuncAttributeMaxDynamicSharedMemorySize, SM_IN);
    cudaFuncSetAttribute(gemm_sp<64, 128, 2, 4, 2>,
                         cudaFuncAttributeMaxDynamicSharedMemorySize, SM_X);
    cudaFuncSetAttribute(gemm_sp<64, 128, 2, 4, 1>,
                         cudaFuncAttributeMaxDynamicSharedMemorySize, SM_OUT);

    embed_kernel<<<(NROWS * DM + 255) / 256, 256>>>(x, bw, bb, ge, me);
    wsplit_kernel<<<(4 * 1024 * DM + 255) / 256, 256>>>(ipw, p_wih, p_wil, 4 * 1024 * DM);

    const int SCAN_GRID = BATCH * NCH * 64;   // 3200

    for (int i = 0; i < 4; i++) {
        ln_kernel<<<(NROWS + 7) / 8, 256>>>(p_h, lnw + i * DM, lnb + i * DM,
                                            nullptr, p_lnh, p_lnl);
        {   // launch 4 (i=0): in_proj — profiled slot; 128x128 tile (measured best)
            dim3 grid(1024 / 128, (NROWS + 127) / 128);
            gemm_sp<128, 128, 2, 4, 0><<<grid, 256, SM_IN>>>(
                p_lnh, p_lnl, p_wih + (size_t)i * 1024 * DM, p_wil + (size_t)i * 1024 * DM,
                p_xz, nullptr, nullptr, NROWS, 1024, DM);
        }
        if (i == 0) {
            wbig_kernel<<<4 * NBIG, 256>>>(xpw, dtw);
            wsplit_kernel<<<(4 * DM * DI + 255) / 256, 256>>>(opw, p_woh, p_wol, 4 * DM * DI);
        }
        conv_silu_kernel<<<(NROWS * DI + 255) / 256, 256>>>(cw + i * DI * 4, cb + i * DI);
        {   // x_proj + dt fused: M=4000, N=544, K=512
            dim3 grid((NBIG + 127) / 128, (NROWS + 63) / 64);
            gemm_sp<64, 128, 2, 4, 2><<<grid, 256, SM_X>>>(
                p_uh, p_ul, p_wbh + (size_t)i * NBIG * DI, p_wbl + (size_t)i * NBIG * DI,
                p_bc, dtb + i * DI, p_dt, NROWS, NBIG, DI);
        }
        scan1_kernel<<<SCAN_GRID, 128>>>(alog + (size_t)i * DI * DS);
        scan2_kernel<<<SCAN_GRID, 128>>>(alog + (size_t)i * DI * DS, Dv + i * DI);
        {   // out_proj + residual
            dim3 grid(256 / 128, (NROWS + 63) / 64);
            gemm_sp<64, 128, 2, 4, 1><<<grid, 256, SM_OUT>>>(
                p_yh, p_yl, p_woh + (size_t)i * DM * DI, p_wol + (size_t)i * DM * DI,
                p_h, p_h, nullptr, NROWS, 256, DI);
        }
    }

    ln_kernel<<<(NROWS + 7) / 8, 256>>>(p_h, fw, fb, p_ln, nullptr, nullptr);
    head_kernel<<<(NROWS + 7) / 8, 256>>>(hw, hb, out);
}